// round 1
// baseline (speedup 1.0000x reference)
#include <cuda_runtime.h>
#include <math.h>

// Problem constants (fixed shapes per reference)
#define NU_  40000
#define NI_  60000
#define NN_  100000
#define DF_  1024
#define DL_  128
#define DI_  64
#define NE_  1600000

// Scratch buffers (device globals: allocation-guard safe)
__device__ float g_x   [(size_t)NN_ * DL_];   // normalized x [N,128]
__device__ float g_xw  [(size_t)NN_ * DL_];   // conv output  [N,128] (reused [N,64])
__device__ float g_h   [(size_t)NN_ * DL_];   // segment sum  [N,128] (reused [N,64])
__device__ float g_xhat[(size_t)NN_ * DI_];   // x_hat        [N,64]
__device__ float g_x2  [(size_t)NN_ * DI_];   // layer-1 out  [N,64]

__device__ __forceinline__ float leaky_(float v) { return v > 0.0f ? v : 0.01f * v; }

// ---------------------------------------------------------------------------
// Generic tiled SGEMM: C[M,BN] = op(A[M,K]) @ B   (+bias, +pre, act, +post)
//   TRANSB=false: B is [K,BN] row-major (x @ W)
//   TRANSB=true : B is [BN,K] row-major (x @ W^T)
//   ACTA: apply leaky to A elements on load (used for h)
// Epilogue: v = acc + bias[c] + pre[r,c]; if(act) v=leaky(v); v += post[r,c]
// ---------------------------------------------------------------------------
template <int BN, bool TRANSB, bool ACTA>
__global__ __launch_bounds__(256) void gemm_kernel(
    const float* __restrict__ A, const float* __restrict__ B,
    float* __restrict__ C, int M, int K,
    const float* __restrict__ bias, const float* __restrict__ pre,
    const float* __restrict__ post, int do_act)
{
    constexpr int BM = 64, BK = 32, TM = 4, TN = BN / 16;
    __shared__ __align__(16) float sA[BK][BM + 4];
    __shared__ __align__(16) float sB[BK][BN + 4];

    const int t  = threadIdx.x;
    const int ty = t >> 4;        // 0..15 -> row group
    const int tx = t & 15;        // 0..15 -> col group
    const int m0 = blockIdx.x * BM;

    float acc[TM][TN];
#pragma unroll
    for (int i = 0; i < TM; i++)
#pragma unroll
        for (int j = 0; j < TN; j++) acc[i][j] = 0.0f;

    for (int k0 = 0; k0 < K; k0 += BK) {
        // ---- load A tile (BM x BK), store transposed sA[k][r] ----
#pragma unroll
        for (int i = 0; i < (BM * BK) / (256 * 4); i++) {
            int fid = t + i * 256;
            int r   = fid >> 3;      // BK/4 = 8 float4 per row
            int k4  = fid & 7;
            int row = m0 + r;
            float4 av = make_float4(0.f, 0.f, 0.f, 0.f);
            if (row < M) av = *(const float4*)&A[(size_t)row * K + k0 + k4 * 4];
            if (ACTA) {
                av.x = leaky_(av.x); av.y = leaky_(av.y);
                av.z = leaky_(av.z); av.w = leaky_(av.w);
            }
            sA[k4 * 4 + 0][r] = av.x; sA[k4 * 4 + 1][r] = av.y;
            sA[k4 * 4 + 2][r] = av.z; sA[k4 * 4 + 3][r] = av.w;
        }
        // ---- load B tile (BK x BN) ----
        if (TRANSB) {
#pragma unroll
            for (int i = 0; i < (BK * BN) / (256 * 4); i++) {
                int fid = t + i * 256;
                int n   = fid >> 3;
                int k4  = fid & 7;
                float4 bv = *(const float4*)&B[(size_t)n * K + k0 + k4 * 4];
                sB[k4 * 4 + 0][n] = bv.x; sB[k4 * 4 + 1][n] = bv.y;
                sB[k4 * 4 + 2][n] = bv.z; sB[k4 * 4 + 3][n] = bv.w;
            }
        } else {
#pragma unroll
            for (int i = 0; i < (BK * BN) / (256 * 4); i++) {
                int fid = t + i * 256;
                int kk  = fid / (BN / 4);
                int n4  = fid % (BN / 4);
                float4 bv = *(const float4*)&B[(size_t)(k0 + kk) * BN + n4 * 4];
                *(float4*)&sB[kk][n4 * 4] = bv;
            }
        }
        __syncthreads();

        // ---- compute ----
#pragma unroll
        for (int k = 0; k < BK; k++) {
            float4 a4 = *(const float4*)&sA[k][ty * TM];
            float av[TM] = {a4.x, a4.y, a4.z, a4.w};
            float bv[TN];
#pragma unroll
            for (int j = 0; j < TN; j += 4) {
                float4 b4 = *(const float4*)&sB[k][tx * TN + j];
                bv[j] = b4.x; bv[j + 1] = b4.y; bv[j + 2] = b4.z; bv[j + 3] = b4.w;
            }
#pragma unroll
            for (int i = 0; i < TM; i++)
#pragma unroll
                for (int j = 0; j < TN; j++) acc[i][j] += av[i] * bv[j];
        }
        __syncthreads();
    }

    // ---- epilogue ----
#pragma unroll
    for (int i = 0; i < TM; i++) {
        int row = m0 + ty * TM + i;
        if (row >= M) continue;
#pragma unroll
        for (int j = 0; j < TN; j++) {
            int c = tx * TN + j;
            float v = acc[i][j];
            if (bias) v += bias[c];
            if (pre)  v += pre[(size_t)row * BN + c];
            if (do_act) v = leaky_(v);
            if (post) v += post[(size_t)row * BN + c];
            C[(size_t)row * BN + c] = v;
        }
    }
}

// ---------------------------------------------------------------------------
// Row-wise L2 normalize, D=128 (one warp per row, one float4 per lane)
// ---------------------------------------------------------------------------
__global__ void normalize_kernel(float* __restrict__ x, int nrows)
{
    int warp = (blockIdx.x * blockDim.x + threadIdx.x) >> 5;
    int lane = threadIdx.x & 31;
    if (warp >= nrows) return;
    float4 v = *(const float4*)&x[(size_t)warp * 128 + lane * 4];
    float ss = v.x * v.x + v.y * v.y + v.z * v.z + v.w * v.w;
#pragma unroll
    for (int o = 16; o; o >>= 1) ss += __shfl_xor_sync(0xffffffffu, ss, o);
    float inv = 1.0f / fmaxf(sqrtf(ss), 1e-12f);
    v.x *= inv; v.y *= inv; v.z *= inv; v.w *= inv;
    *(float4*)&x[(size_t)warp * 128 + lane * 4] = v;
}

// ---------------------------------------------------------------------------
// Zero buffer (float4 stores)
// ---------------------------------------------------------------------------
__global__ void zero_kernel(float4* __restrict__ p, int n4)
{
    int i = blockIdx.x * blockDim.x + threadIdx.x;
    if (i < n4) p[i] = make_float4(0.f, 0.f, 0.f, 0.f);
}

// ---------------------------------------------------------------------------
// Edge scatter: h[dst] += xw[src], D floats/edge, one float4 per thread.
// Edge src/dst reads broadcast within warp (same address for D/4 lanes).
// ---------------------------------------------------------------------------
template <int D>
__global__ void scatter_kernel(const float* __restrict__ xw,
                               const int* __restrict__ ei,
                               float* __restrict__ h)
{
    constexpr int G = D / 4;
    int idx = blockIdx.x * blockDim.x + threadIdx.x;
    if (idx >= NE_ * G) return;
    int e = idx / G;
    int q = idx - e * G;
    int src = __ldg(&ei[e]);
    int dst = __ldg(&ei[NE_ + e]);
    float4 v = *(const float4*)&xw[(size_t)src * D + q * 4];
    float* hp = &h[(size_t)dst * D + q * 4];
    atomicAdd(hp + 0, v.x);
    atomicAdd(hp + 1, v.y);
    atomicAdd(hp + 2, v.z);
    atomicAdd(hp + 3, v.w);
}

// ---------------------------------------------------------------------------
extern "C" void kernel_launch(void* const* d_in, const int* in_sizes, int n_in,
                              void* d_out, int out_size)
{
    const float* features = (const float*)d_in[0];
    const float* id_emb   = (const float*)d_in[1];
    const float* pref     = (const float*)d_in[2];
    const float* mlp_w    = (const float*)d_in[3];
    const float* mlp_b    = (const float*)d_in[4];
    const float* conv1_w  = (const float*)d_in[5];
    const float* lin1_w   = (const float*)d_in[6];
    const float* lin1_b   = (const float*)d_in[7];
    const float* g1_w     = (const float*)d_in[8];
    const float* g1_b     = (const float*)d_in[9];
    const float* conv2_w  = (const float*)d_in[10];
    const float* lin2_w   = (const float*)d_in[11];
    const float* lin2_b   = (const float*)d_in[12];
    const float* g2_w     = (const float*)d_in[13];
    const float* g2_b     = (const float*)d_in[14];
    const int*   ei       = (const int*)d_in[15];
    float* out = (float*)d_out;

    float *px, *pxw, *ph, *pxhat, *px2;
    cudaGetSymbolAddress((void**)&px,    g_x);
    cudaGetSymbolAddress((void**)&pxw,   g_xw);
    cudaGetSymbolAddress((void**)&ph,    g_h);
    cudaGetSymbolAddress((void**)&pxhat, g_xhat);
    cudaGetSymbolAddress((void**)&px2,   g_x2);

    const int GB_N = (NN_ + 63) / 64;

    // x[:NU] = preference
    cudaMemcpyAsync(px, pref, (size_t)NU_ * DL_ * sizeof(float),
                    cudaMemcpyDeviceToDevice, 0);

    // x[NU:] = features @ mlp_w^T + mlp_b
    gemm_kernel<128, true, false><<<(NI_ + 63) / 64, 256>>>(
        features, mlp_w, px + (size_t)NU_ * DL_, NI_, DF_, mlp_b, nullptr, nullptr, 0);

    // row-wise L2 normalize
    normalize_kernel<<<(NN_ * 32 + 255) / 256, 256>>>(px, NN_);

    // ===== layer 1 =====
    // xw = x @ conv1_w
    gemm_kernel<128, false, false><<<GB_N, 256>>>(
        px, conv1_w, pxw, NN_, DL_, nullptr, nullptr, nullptr, 0);
    // h = segment_sum(xw[src] -> dst)
    zero_kernel<<<(NN_ * DL_ / 4 + 255) / 256, 256>>>((float4*)ph, NN_ * DL_ / 4);
    scatter_kernel<128><<<(NE_ * 32 + 255) / 256, 256>>>(pxw, ei, ph);
    // x_hat = leaky(x @ lin1_w^T + lin1_b) + id_embedding
    gemm_kernel<64, true, false><<<GB_N, 256>>>(
        px, lin1_w, pxhat, NN_, DL_, lin1_b, nullptr, id_emb, 1);
    // x2 = leaky(leaky(h) @ g1_w^T + g1_b + x_hat)
    gemm_kernel<64, true, true><<<GB_N, 256>>>(
        ph, g1_w, px2, NN_, DL_, g1_b, pxhat, nullptr, 1);

    // ===== layer 2 =====
    // xw = x2 @ conv2_w
    gemm_kernel<64, false, false><<<GB_N, 256>>>(
        px2, conv2_w, pxw, NN_, DI_, nullptr, nullptr, nullptr, 0);
    zero_kernel<<<(NN_ * DI_ / 4 + 255) / 256, 256>>>((float4*)ph, NN_ * DI_ / 4);
    scatter_kernel<64><<<(NE_ * 16 + 255) / 256, 256>>>(pxw, ei, ph);
    // x_hat = leaky(x2 @ lin2_w^T + lin2_b) + id_embedding
    gemm_kernel<64, true, false><<<GB_N, 256>>>(
        px2, lin2_w, pxhat, NN_, DI_, lin2_b, nullptr, id_emb, 1);
    // out = leaky(leaky(h) @ g2_w^T + g2_b + x_hat)
    gemm_kernel<64, true, true><<<GB_N, 256>>>(
        ph, g2_w, out, NN_, DI_, g2_b, pxhat, nullptr, 1);
}

// round 2
// speedup vs baseline: 2.1569x; 2.1569x over previous
#include <cuda_runtime.h>
#include <math.h>

// Problem constants (fixed shapes per reference)
#define NU_  40000
#define NI_  60000
#define NN_  100000
#define DF_  1024
#define DL_  128
#define DI_  64
#define NE_  1600000

// Scratch buffers (device globals: allocation-guard safe)
__device__ float g_x   [(size_t)NN_ * DL_];   // normalized x [N,128]
__device__ float g_xw  [(size_t)NN_ * DL_];   // conv output  [N,128] (reused [N,64])
__device__ float g_h   [(size_t)NN_ * DL_];   // segment sum  [N,128] (reused [N,64])
__device__ float g_xhat[(size_t)NN_ * DI_];   // x_hat        [N,64]
__device__ float g_x2  [(size_t)NN_ * DI_];   // layer-1 out  [N,64]

__device__ __forceinline__ float leaky_(float v) { return v > 0.0f ? v : 0.01f * v; }

__device__ __forceinline__ float to_tf32(float x) {
    float r;
    asm("cvt.rna.tf32.f32 %0, %1;" : "=f"(r) : "f"(x));
    return r;
}

__device__ __forceinline__ void mma_tf32(float* d, const unsigned* a, const unsigned* b) {
    asm volatile(
        "mma.sync.aligned.m16n8k8.row.col.f32.tf32.tf32.f32 "
        "{%0,%1,%2,%3}, {%4,%5,%6,%7}, {%8,%9}, {%0,%1,%2,%3};"
        : "+f"(d[0]), "+f"(d[1]), "+f"(d[2]), "+f"(d[3])
        : "r"(a[0]), "r"(a[1]), "r"(a[2]), "r"(a[3]), "r"(b[0]), "r"(b[1]));
}

// ---------------------------------------------------------------------------
// tf32 tensor-core GEMM: C[M,BN] = op(A[M,K]) @ B  (+bias, +pre, act, +post)
//   TRANSB=false: B is [K,BN] row-major (x @ W)
//   TRANSB=true : B is [BN,K] row-major (x @ W^T)
//   ACTA: apply leaky to A elements while filling smem (used for h)
// Epilogue: v = acc + bias[c] + pre[r,c]; if(act) v=leaky(v); v += post[r,c]
// Block tile 128 x BN, BK=32, 256 threads (8 warps).
// ---------------------------------------------------------------------------
template <int BN, bool TRANSB, bool ACTA>
__global__ __launch_bounds__(256) void mma_gemm(
    const float* __restrict__ A, const float* __restrict__ B,
    float* __restrict__ C, int M, int K,
    const float* __restrict__ bias, const float* __restrict__ pre,
    const float* __restrict__ post, int do_act)
{
    constexpr int BM = 128, BK = 32;
    constexpr int WARPS_M = (BN == 128) ? 2 : 4;
    constexpr int WARPS_N = 8 / WARPS_M;
    constexpr int WM = BM / WARPS_M;   // 64 or 32
    constexpr int WN = BN / WARPS_N;   // 32
    constexpr int MT = WM / 16;        // 4 or 2
    constexpr int NT = WN / 8;         // 4

    __shared__ __align__(16) float sA[BM][BK + 4];
    // TRANSB: sB[n][k] with pad 4; else sB[k][n] with pad 8 (both conflict-free)
    constexpr int SB_ROWS = TRANSB ? BN : BK;
    constexpr int SB_COLS = TRANSB ? (BK + 4) : (BN + 8);
    __shared__ __align__(16) float sB[SB_ROWS][SB_COLS];

    const int t    = threadIdx.x;
    const int wid  = t >> 5;
    const int lane = t & 31;
    const int gid  = lane >> 2;   // group id (0..7)
    const int tidg = lane & 3;    // thread in group (0..3)
    const int wm   = (wid % WARPS_M) * WM;
    const int wn   = (wid / WARPS_M) * WN;
    const int m0   = blockIdx.x * BM;

    float acc[MT][NT][4];
#pragma unroll
    for (int i = 0; i < MT; i++)
#pragma unroll
        for (int j = 0; j < NT; j++)
#pragma unroll
            for (int q = 0; q < 4; q++) acc[i][j][q] = 0.0f;

    for (int k0 = 0; k0 < K; k0 += BK) {
        // ---- A tile: BM x BK, float4 loads along K ----
#pragma unroll
        for (int i = 0; i < (BM * BK) / (256 * 4); i++) {
            int fid = t + i * 256;
            int r   = fid >> 3;   // BK/4 = 8 float4 per row
            int k4  = fid & 7;
            int row = m0 + r;
            float4 av = make_float4(0.f, 0.f, 0.f, 0.f);
            if (row < M) av = *(const float4*)&A[(size_t)row * K + k0 + k4 * 4];
            if (ACTA) {
                av.x = leaky_(av.x); av.y = leaky_(av.y);
                av.z = leaky_(av.z); av.w = leaky_(av.w);
            }
            av.x = to_tf32(av.x); av.y = to_tf32(av.y);
            av.z = to_tf32(av.z); av.w = to_tf32(av.w);
            *(float4*)&sA[r][k4 * 4] = av;
        }
        // ---- B tile ----
        if (TRANSB) {
#pragma unroll
            for (int i = 0; i < (BN * BK) / (256 * 4); i++) {
                int fid = t + i * 256;
                int n   = fid >> 3;
                int k4  = fid & 7;
                float4 bv = *(const float4*)&B[(size_t)n * K + k0 + k4 * 4];
                bv.x = to_tf32(bv.x); bv.y = to_tf32(bv.y);
                bv.z = to_tf32(bv.z); bv.w = to_tf32(bv.w);
                *(float4*)&sB[n][k4 * 4] = bv;
            }
        } else {
#pragma unroll
            for (int i = 0; i < (BK * BN) / (256 * 4); i++) {
                int fid = t + i * 256;
                int kk  = fid / (BN / 4);
                int n4  = fid % (BN / 4);
                float4 bv = *(const float4*)&B[(size_t)(k0 + kk) * BN + n4 * 4];
                bv.x = to_tf32(bv.x); bv.y = to_tf32(bv.y);
                bv.z = to_tf32(bv.z); bv.w = to_tf32(bv.w);
                *(float4*)&sB[kk][n4 * 4] = bv;
            }
        }
        __syncthreads();

        // ---- compute: 4 k8-steps ----
#pragma unroll
        for (int kk = 0; kk < BK; kk += 8) {
            unsigned afrag[MT][4];
#pragma unroll
            for (int mt = 0; mt < MT; mt++) {
                int r = wm + mt * 16 + gid;
                afrag[mt][0] = __float_as_uint(sA[r][kk + tidg]);
                afrag[mt][1] = __float_as_uint(sA[r + 8][kk + tidg]);
                afrag[mt][2] = __float_as_uint(sA[r][kk + tidg + 4]);
                afrag[mt][3] = __float_as_uint(sA[r + 8][kk + tidg + 4]);
            }
            unsigned bfrag[NT][2];
#pragma unroll
            for (int nt = 0; nt < NT; nt++) {
                int n = wn + nt * 8 + gid;
                if (TRANSB) {
                    bfrag[nt][0] = __float_as_uint(sB[n][kk + tidg]);
                    bfrag[nt][1] = __float_as_uint(sB[n][kk + tidg + 4]);
                } else {
                    bfrag[nt][0] = __float_as_uint(sB[kk + tidg][n]);
                    bfrag[nt][1] = __float_as_uint(sB[kk + tidg + 4][n]);
                }
            }
#pragma unroll
            for (int mt = 0; mt < MT; mt++)
#pragma unroll
                for (int nt = 0; nt < NT; nt++)
                    mma_tf32(acc[mt][nt], afrag[mt], bfrag[nt]);
        }
        __syncthreads();
    }

    // ---- epilogue: each thread owns (row, col..col+1) and (row+8, ...) ----
#pragma unroll
    for (int mt = 0; mt < MT; mt++) {
#pragma unroll
        for (int nt = 0; nt < NT; nt++) {
            int col = wn + nt * 8 + 2 * tidg;
#pragma unroll
            for (int half = 0; half < 2; half++) {
                int row = m0 + wm + mt * 16 + gid + half * 8;
                if (row >= M) continue;
                float v0 = acc[mt][nt][half * 2 + 0];
                float v1 = acc[mt][nt][half * 2 + 1];
                if (bias) { v0 += bias[col]; v1 += bias[col + 1]; }
                if (pre)  {
                    v0 += pre[(size_t)row * BN + col];
                    v1 += pre[(size_t)row * BN + col + 1];
                }
                if (do_act) { v0 = leaky_(v0); v1 = leaky_(v1); }
                if (post) {
                    v0 += post[(size_t)row * BN + col];
                    v1 += post[(size_t)row * BN + col + 1];
                }
                *(float2*)&C[(size_t)row * BN + col] = make_float2(v0, v1);
            }
        }
    }
}

// ---------------------------------------------------------------------------
// Row-wise L2 normalize, D=128 (one warp per row)
// ---------------------------------------------------------------------------
__global__ void normalize_kernel(float* __restrict__ x, int nrows)
{
    int warp = (blockIdx.x * blockDim.x + threadIdx.x) >> 5;
    int lane = threadIdx.x & 31;
    if (warp >= nrows) return;
    float4 v = *(const float4*)&x[(size_t)warp * 128 + lane * 4];
    float ss = v.x * v.x + v.y * v.y + v.z * v.z + v.w * v.w;
#pragma unroll
    for (int o = 16; o; o >>= 1) ss += __shfl_xor_sync(0xffffffffu, ss, o);
    float inv = 1.0f / fmaxf(sqrtf(ss), 1e-12f);
    v.x *= inv; v.y *= inv; v.z *= inv; v.w *= inv;
    *(float4*)&x[(size_t)warp * 128 + lane * 4] = v;
}

__global__ void zero_kernel(float4* __restrict__ p, int n4)
{
    int i = blockIdx.x * blockDim.x + threadIdx.x;
    if (i < n4) p[i] = make_float4(0.f, 0.f, 0.f, 0.f);
}

// ---------------------------------------------------------------------------
// Edge scatter: h[dst] += xw[src], vectorized red.global.add.v4.f32
// ---------------------------------------------------------------------------
template <int D>
__global__ void scatter_kernel(const float* __restrict__ xw,
                               const int* __restrict__ ei,
                               float* __restrict__ h)
{
    constexpr int G = D / 4;
    int idx = blockIdx.x * blockDim.x + threadIdx.x;
    if (idx >= NE_ * G) return;
    int e = idx / G;
    int q = idx - e * G;
    int src = __ldg(&ei[e]);
    int dst = __ldg(&ei[NE_ + e]);
    float4 v = *(const float4*)&xw[(size_t)src * D + q * 4];
    float* hp = &h[(size_t)dst * D + q * 4];
    asm volatile("red.global.add.v4.f32 [%0], {%1, %2, %3, %4};"
                 :: "l"(hp), "f"(v.x), "f"(v.y), "f"(v.z), "f"(v.w)
                 : "memory");
}

// ---------------------------------------------------------------------------
extern "C" void kernel_launch(void* const* d_in, const int* in_sizes, int n_in,
                              void* d_out, int out_size)
{
    const float* features = (const float*)d_in[0];
    const float* id_emb   = (const float*)d_in[1];
    const float* pref     = (const float*)d_in[2];
    const float* mlp_w    = (const float*)d_in[3];
    const float* mlp_b    = (const float*)d_in[4];
    const float* conv1_w  = (const float*)d_in[5];
    const float* lin1_w   = (const float*)d_in[6];
    const float* lin1_b   = (const float*)d_in[7];
    const float* g1_w     = (const float*)d_in[8];
    const float* g1_b     = (const float*)d_in[9];
    const float* conv2_w  = (const float*)d_in[10];
    const float* lin2_w   = (const float*)d_in[11];
    const float* lin2_b   = (const float*)d_in[12];
    const float* g2_w     = (const float*)d_in[13];
    const float* g2_b     = (const float*)d_in[14];
    const int*   ei       = (const int*)d_in[15];
    float* out = (float*)d_out;

    float *px, *pxw, *ph, *pxhat, *px2;
    cudaGetSymbolAddress((void**)&px,    g_x);
    cudaGetSymbolAddress((void**)&pxw,   g_xw);
    cudaGetSymbolAddress((void**)&ph,    g_h);
    cudaGetSymbolAddress((void**)&pxhat, g_xhat);
    cudaGetSymbolAddress((void**)&px2,   g_x2);

    const int GB_N = (NN_ + 127) / 128;

    // x[:NU] = preference
    cudaMemcpyAsync(px, pref, (size_t)NU_ * DL_ * sizeof(float),
                    cudaMemcpyDeviceToDevice, 0);

    // x[NU:] = features @ mlp_w^T + mlp_b
    mma_gemm<128, true, false><<<(NI_ + 127) / 128, 256>>>(
        features, mlp_w, px + (size_t)NU_ * DL_, NI_, DF_, mlp_b, nullptr, nullptr, 0);

    // row-wise L2 normalize
    normalize_kernel<<<(NN_ * 32 + 255) / 256, 256>>>(px, NN_);

    // ===== layer 1 =====
    mma_gemm<128, false, false><<<GB_N, 256>>>(
        px, conv1_w, pxw, NN_, DL_, nullptr, nullptr, nullptr, 0);
    zero_kernel<<<(NN_ * DL_ / 4 + 255) / 256, 256>>>((float4*)ph, NN_ * DL_ / 4);
    scatter_kernel<128><<<(NE_ * 32 + 255) / 256, 256>>>(pxw, ei, ph);
    mma_gemm<64, true, false><<<GB_N, 256>>>(
        px, lin1_w, pxhat, NN_, DL_, lin1_b, nullptr, id_emb, 1);
    mma_gemm<64, true, true><<<GB_N, 256>>>(
        ph, g1_w, px2, NN_, DL_, g1_b, pxhat, nullptr, 1);

    // ===== layer 2 =====
    mma_gemm<64, false, false><<<GB_N, 256>>>(
        px2, conv2_w, pxw, NN_, DI_, nullptr, nullptr, nullptr, 0);
    zero_kernel<<<(NN_ * DI_ / 4 + 255) / 256, 256>>>((float4*)ph, NN_ * DI_ / 4);
    scatter_kernel<64><<<(NE_ * 16 + 255) / 256, 256>>>(pxw, ei, ph);
    mma_gemm<64, true, false><<<GB_N, 256>>>(
        px2, lin2_w, pxhat, NN_, DI_, lin2_b, nullptr, id_emb, 1);
    mma_gemm<64, true, true><<<GB_N, 256>>>(
        ph, g2_w, out, NN_, DI_, g2_b, pxhat, nullptr, 1);
}

// round 3
// speedup vs baseline: 2.4719x; 1.1460x over previous
#include <cuda_runtime.h>
#include <math.h>

// Problem constants (fixed shapes per reference)
#define NU_  40000
#define NI_  60000
#define NN_  100000
#define DF_  1024
#define DL_  128
#define DI_  64
#define NE_  1600000

// Scratch buffers (device globals: allocation-guard safe)
__device__ float g_x   [(size_t)NN_ * DL_];   // normalized x [N,128]
__device__ float g_xw  [(size_t)NN_ * DL_];   // conv output  [N,128] (reused [N,64])
__device__ float g_h   [(size_t)NN_ * DL_];   // segment sum  [N,128] (reused [N,64])
__device__ float g_xhat[(size_t)NN_ * DI_];   // x_hat        [N,64]
__device__ float g_x2  [(size_t)NN_ * DI_];   // layer-1 out  [N,64]

__device__ __forceinline__ float leaky_(float v) { return v > 0.0f ? v : 0.01f * v; }

__device__ __forceinline__ float to_tf32(float x) {
    float r;
    asm("cvt.rna.tf32.f32 %0, %1;" : "=f"(r) : "f"(x));
    return r;
}

__device__ __forceinline__ void mma_tf32(float* d, const unsigned* a, const unsigned* b) {
    asm volatile(
        "mma.sync.aligned.m16n8k8.row.col.f32.tf32.tf32.f32 "
        "{%0,%1,%2,%3}, {%4,%5,%6,%7}, {%8,%9}, {%0,%1,%2,%3};"
        : "+f"(d[0]), "+f"(d[1]), "+f"(d[2]), "+f"(d[3])
        : "r"(a[0]), "r"(a[1]), "r"(a[2]), "r"(a[3]), "r"(b[0]), "r"(b[1]));
}

// ---------------------------------------------------------------------------
// Pipelined tf32 tensor-core GEMM: C[M,BN] = op(A[M,K]) @ B
//   TRANSB=false: B is [K,BN] row-major (x @ W)
//   TRANSB=true : B is [BN,K] row-major (x @ W^T)
//   ACTA: apply leaky to A elements while filling smem (used for h)
//   NORM: row-wise L2-normalize the output (MLP path; bias applied first,
//         pre/post/act unused). BN must equal the full row width.
// Epilogue (non-NORM): v = acc + bias[c] + pre[r,c]; if(act) leaky; v += post.
// Block tile 128 x BN, BK=16 double-buffered, 256 threads (8 warps).
// ---------------------------------------------------------------------------
template <int BN, bool TRANSB, bool ACTA, bool NORM>
__global__ __launch_bounds__(256) void mma_gemm(
    const float* __restrict__ A, const float* __restrict__ B,
    float* __restrict__ C, int M, int K,
    const float* __restrict__ bias, const float* __restrict__ pre,
    const float* __restrict__ post, int do_act)
{
    constexpr int BM = 128, BK = 16;
    constexpr int WARPS_M = (BN == 128) ? 2 : 4;
    constexpr int WARPS_N = 8 / WARPS_M;
    constexpr int WM = BM / WARPS_M;   // 64 or 32
    constexpr int WN = BN / WARPS_N;   // 32
    constexpr int MT = WM / 16;        // 4 or 2
    constexpr int NT = WN / 8;         // 4

    __shared__ __align__(16) float sA[2][BM][BK + 4];
    constexpr int SB_ROWS = TRANSB ? BN : BK;
    constexpr int SB_COLS = TRANSB ? (BK + 4) : (BN + 8);
    __shared__ __align__(16) float sB[2][SB_ROWS][SB_COLS];
    __shared__ float sNorm[NORM ? BM : 1];

    const int t    = threadIdx.x;
    const int wid  = t >> 5;
    const int lane = t & 31;
    const int gid  = lane >> 2;
    const int tidg = lane & 3;
    const int wm   = (wid % WARPS_M) * WM;
    const int wn   = (wid / WARPS_M) * WN;
    const int m0   = blockIdx.x * BM;

    constexpr int A_LD = (BM * BK) / (256 * 4);   // 2
    constexpr int B_LD = (BN * BK) / (256 * 4);   // 2 or 1

    float4 aReg[A_LD], bReg[B_LD];

    float acc[MT][NT][4];
#pragma unroll
    for (int i = 0; i < MT; i++)
#pragma unroll
        for (int j = 0; j < NT; j++)
#pragma unroll
            for (int q = 0; q < 4; q++) acc[i][j][q] = 0.0f;

    // ---- load helpers (inlined via macros on unrolled loops) ----
#define LOAD_A(K0)                                                          \
    _Pragma("unroll")                                                       \
    for (int i = 0; i < A_LD; i++) {                                        \
        int fid = t + i * 256;                                              \
        int r = fid >> 2, k4 = fid & 3;                                     \
        int row = m0 + r;                                                   \
        float4 v = make_float4(0.f, 0.f, 0.f, 0.f);                         \
        if (row < M) v = *(const float4*)&A[(size_t)row * K + (K0) + k4*4]; \
        aReg[i] = v;                                                        \
    }

#define STORE_A(BUF)                                                        \
    _Pragma("unroll")                                                       \
    for (int i = 0; i < A_LD; i++) {                                        \
        int fid = t + i * 256;                                              \
        int r = fid >> 2, k4 = fid & 3;                                     \
        float4 v = aReg[i];                                                 \
        if (ACTA) { v.x = leaky_(v.x); v.y = leaky_(v.y);                   \
                    v.z = leaky_(v.z); v.w = leaky_(v.w); }                 \
        v.x = to_tf32(v.x); v.y = to_tf32(v.y);                             \
        v.z = to_tf32(v.z); v.w = to_tf32(v.w);                             \
        *(float4*)&sA[BUF][r][k4 * 4] = v;                                  \
    }

#define LOAD_B(K0)                                                          \
    _Pragma("unroll")                                                       \
    for (int i = 0; i < B_LD; i++) {                                        \
        int fid = t + i * 256;                                              \
        if (TRANSB) {                                                       \
            int n = fid >> 2, k4 = fid & 3;                                 \
            bReg[i] = *(const float4*)&B[(size_t)n * K + (K0) + k4 * 4];    \
        } else {                                                            \
            int kk = fid / (BN / 4), n4 = fid % (BN / 4);                   \
            bReg[i] = *(const float4*)&B[(size_t)((K0) + kk) * BN + n4*4];  \
        }                                                                   \
    }

#define STORE_B(BUF)                                                        \
    _Pragma("unroll")                                                       \
    for (int i = 0; i < B_LD; i++) {                                        \
        int fid = t + i * 256;                                              \
        float4 v = bReg[i];                                                 \
        v.x = to_tf32(v.x); v.y = to_tf32(v.y);                             \
        v.z = to_tf32(v.z); v.w = to_tf32(v.w);                             \
        if (TRANSB) {                                                       \
            int n = fid >> 2, k4 = fid & 3;                                 \
            *(float4*)&sB[BUF][n][k4 * 4] = v;                              \
        } else {                                                            \
            int kk = fid / (BN / 4), n4 = fid % (BN / 4);                   \
            *(float4*)&sB[BUF][kk][n4 * 4] = v;                             \
        }                                                                   \
    }

    const int nk = K / BK;

    LOAD_A(0); LOAD_B(0);
    STORE_A(0); STORE_B(0);
    __syncthreads();

    for (int it = 0; it < nk; it++) {
        const int buf = it & 1;
        if (it + 1 < nk) { LOAD_A((it + 1) * BK); LOAD_B((it + 1) * BK); }

        // ---- compute current tile: 2 k8-steps ----
#pragma unroll
        for (int kk = 0; kk < BK; kk += 8) {
            unsigned afrag[MT][4];
#pragma unroll
            for (int mt = 0; mt < MT; mt++) {
                int r = wm + mt * 16 + gid;
                afrag[mt][0] = __float_as_uint(sA[buf][r][kk + tidg]);
                afrag[mt][1] = __float_as_uint(sA[buf][r + 8][kk + tidg]);
                afrag[mt][2] = __float_as_uint(sA[buf][r][kk + tidg + 4]);
                afrag[mt][3] = __float_as_uint(sA[buf][r + 8][kk + tidg + 4]);
            }
            unsigned bfrag[NT][2];
#pragma unroll
            for (int nt = 0; nt < NT; nt++) {
                int n = wn + nt * 8 + gid;
                if (TRANSB) {
                    bfrag[nt][0] = __float_as_uint(sB[buf][n][kk + tidg]);
                    bfrag[nt][1] = __float_as_uint(sB[buf][n][kk + tidg + 4]);
                } else {
                    bfrag[nt][0] = __float_as_uint(sB[buf][kk + tidg][n]);
                    bfrag[nt][1] = __float_as_uint(sB[buf][kk + tidg + 4][n]);
                }
            }
#pragma unroll
            for (int mt = 0; mt < MT; mt++)
#pragma unroll
                for (int nt = 0; nt < NT; nt++)
                    mma_tf32(acc[mt][nt], afrag[mt], bfrag[nt]);
        }

        if (it + 1 < nk) {
            STORE_A(buf ^ 1); STORE_B(buf ^ 1);
            __syncthreads();
        }
    }

    // ---- epilogue ----
    if (NORM) {
        if (t < BM) sNorm[t] = 0.0f;
        __syncthreads();
#pragma unroll
        for (int mt = 0; mt < MT; mt++)
#pragma unroll
            for (int nt = 0; nt < NT; nt++) {
                int col = wn + nt * 8 + 2 * tidg;
#pragma unroll
                for (int half = 0; half < 2; half++) {
                    int rl = wm + mt * 16 + gid + half * 8;
                    if (m0 + rl >= M) continue;
                    float v0 = acc[mt][nt][half * 2 + 0] + bias[col];
                    float v1 = acc[mt][nt][half * 2 + 1] + bias[col + 1];
                    acc[mt][nt][half * 2 + 0] = v0;
                    acc[mt][nt][half * 2 + 1] = v1;
                    atomicAdd(&sNorm[rl], v0 * v0 + v1 * v1);
                }
            }
        __syncthreads();
        if (t < BM) sNorm[t] = 1.0f / fmaxf(sqrtf(sNorm[t]), 1e-12f);
        __syncthreads();
#pragma unroll
        for (int mt = 0; mt < MT; mt++)
#pragma unroll
            for (int nt = 0; nt < NT; nt++) {
                int col = wn + nt * 8 + 2 * tidg;
#pragma unroll
                for (int half = 0; half < 2; half++) {
                    int rl = wm + mt * 16 + gid + half * 8;
                    int row = m0 + rl;
                    if (row >= M) continue;
                    float inv = sNorm[rl];
                    float v0 = acc[mt][nt][half * 2 + 0] * inv;
                    float v1 = acc[mt][nt][half * 2 + 1] * inv;
                    *(float2*)&C[(size_t)row * BN + col] = make_float2(v0, v1);
                }
            }
    } else {
#pragma unroll
        for (int mt = 0; mt < MT; mt++)
#pragma unroll
            for (int nt = 0; nt < NT; nt++) {
                int col = wn + nt * 8 + 2 * tidg;
#pragma unroll
                for (int half = 0; half < 2; half++) {
                    int row = m0 + wm + mt * 16 + gid + half * 8;
                    if (row >= M) continue;
                    float v0 = acc[mt][nt][half * 2 + 0];
                    float v1 = acc[mt][nt][half * 2 + 1];
                    if (bias) { v0 += bias[col]; v1 += bias[col + 1]; }
                    if (pre) {
                        v0 += pre[(size_t)row * BN + col];
                        v1 += pre[(size_t)row * BN + col + 1];
                    }
                    if (do_act) { v0 = leaky_(v0); v1 = leaky_(v1); }
                    if (post) {
                        v0 += post[(size_t)row * BN + col];
                        v1 += post[(size_t)row * BN + col + 1];
                    }
                    *(float2*)&C[(size_t)row * BN + col] = make_float2(v0, v1);
                }
            }
    }
#undef LOAD_A
#undef STORE_A
#undef LOAD_B
#undef STORE_B
}

// ---------------------------------------------------------------------------
// Fused copy + row-wise L2 normalize for preference rows (D=128, warp/row)
// ---------------------------------------------------------------------------
__global__ void pref_norm_kernel(const float* __restrict__ src,
                                 float* __restrict__ dst, int nrows)
{
    int warp = (blockIdx.x * blockDim.x + threadIdx.x) >> 5;
    int lane = threadIdx.x & 31;
    if (warp >= nrows) return;
    float4 v = *(const float4*)&src[(size_t)warp * 128 + lane * 4];
    float ss = v.x * v.x + v.y * v.y + v.z * v.z + v.w * v.w;
#pragma unroll
    for (int o = 16; o; o >>= 1) ss += __shfl_xor_sync(0xffffffffu, ss, o);
    float inv = 1.0f / fmaxf(sqrtf(ss), 1e-12f);
    v.x *= inv; v.y *= inv; v.z *= inv; v.w *= inv;
    *(float4*)&dst[(size_t)warp * 128 + lane * 4] = v;
}

// ---------------------------------------------------------------------------
// Edge scatter: h[dst] += xw[src], vectorized red.global.add.v4.f32
// ---------------------------------------------------------------------------
template <int D>
__global__ void scatter_kernel(const float* __restrict__ xw,
                               const int* __restrict__ ei,
                               float* __restrict__ h)
{
    constexpr int G = D / 4;
    int idx = blockIdx.x * blockDim.x + threadIdx.x;
    if (idx >= NE_ * G) return;
    int e = idx / G;
    int q = idx - e * G;
    int src = __ldg(&ei[e]);
    int dst = __ldg(&ei[NE_ + e]);
    float4 v = *(const float4*)&xw[(size_t)src * D + q * 4];
    float* hp = &h[(size_t)dst * D + q * 4];
    asm volatile("red.global.add.v4.f32 [%0], {%1, %2, %3, %4};"
                 :: "l"(hp), "f"(v.x), "f"(v.y), "f"(v.z), "f"(v.w)
                 : "memory");
}

// ---------------------------------------------------------------------------
extern "C" void kernel_launch(void* const* d_in, const int* in_sizes, int n_in,
                              void* d_out, int out_size)
{
    const float* features = (const float*)d_in[0];
    const float* id_emb   = (const float*)d_in[1];
    const float* pref     = (const float*)d_in[2];
    const float* mlp_w    = (const float*)d_in[3];
    const float* mlp_b    = (const float*)d_in[4];
    const float* conv1_w  = (const float*)d_in[5];
    const float* lin1_w   = (const float*)d_in[6];
    const float* lin1_b   = (const float*)d_in[7];
    const float* g1_w     = (const float*)d_in[8];
    const float* g1_b     = (const float*)d_in[9];
    const float* conv2_w  = (const float*)d_in[10];
    const float* lin2_w   = (const float*)d_in[11];
    const float* lin2_b   = (const float*)d_in[12];
    const float* g2_w     = (const float*)d_in[13];
    const float* g2_b     = (const float*)d_in[14];
    const int*   ei       = (const int*)d_in[15];
    float* out = (float*)d_out;

    float *px, *pxw, *ph, *pxhat, *px2;
    cudaGetSymbolAddress((void**)&px,    g_x);
    cudaGetSymbolAddress((void**)&pxw,   g_xw);
    cudaGetSymbolAddress((void**)&ph,    g_h);
    cudaGetSymbolAddress((void**)&pxhat, g_xhat);
    cudaGetSymbolAddress((void**)&px2,   g_x2);

    const int GB_N = (NN_ + 127) / 128;

    // x[:NU] = normalize(preference)
    pref_norm_kernel<<<(NU_ * 32 + 255) / 256, 256>>>(pref, px, NU_);

    // x[NU:] = normalize(features @ mlp_w^T + mlp_b)  (norm fused in epilogue)
    mma_gemm<128, true, false, true><<<(NI_ + 127) / 128, 256>>>(
        features, mlp_w, px + (size_t)NU_ * DL_, NI_, DF_, mlp_b, nullptr, nullptr, 0);

    // ===== layer 1 =====
    mma_gemm<128, false, false, false><<<GB_N, 256>>>(
        px, conv1_w, pxw, NN_, DL_, nullptr, nullptr, nullptr, 0);
    cudaMemsetAsync(ph, 0, (size_t)NN_ * DL_ * sizeof(float), 0);
    scatter_kernel<128><<<(NE_ * 32 + 255) / 256, 256>>>(pxw, ei, ph);
    mma_gemm<64, true, false, false><<<GB_N, 256>>>(
        px, lin1_w, pxhat, NN_, DL_, lin1_b, nullptr, id_emb, 1);
    mma_gemm<64, true, true, false><<<GB_N, 256>>>(
        ph, g1_w, px2, NN_, DL_, g1_b, pxhat, nullptr, 1);

    // ===== layer 2 =====
    mma_gemm<64, false, false, false><<<GB_N, 256>>>(
        px2, conv2_w, pxw, NN_, DI_, nullptr, nullptr, nullptr, 0);
    cudaMemsetAsync(ph, 0, (size_t)NN_ * DI_ * sizeof(float), 0);
    scatter_kernel<64><<<(NE_ * 16 + 255) / 256, 256>>>(pxw, ei, ph);
    mma_gemm<64, true, false, false><<<GB_N, 256>>>(
        px2, lin2_w, pxhat, NN_, DI_, lin2_b, nullptr, id_emb, 1);
    mma_gemm<64, true, true, false><<<GB_N, 256>>>(
        ph, g2_w, out, NN_, DI_, g2_b, pxhat, nullptr, 1);
}

// round 4
// speedup vs baseline: 2.8218x; 1.1416x over previous
#include <cuda_runtime.h>
#include <math.h>

// Problem constants (fixed shapes per reference)
#define NU_  40000
#define NI_  60000
#define NN_  100000
#define DF_  1024
#define DL_  128
#define DI_  64
#define NE_  1600000

// Scratch buffers (device globals: allocation-guard safe)
__device__ float g_x   [(size_t)NN_ * DL_];   // normalized x [N,128]
__device__ float g_xw  [(size_t)NN_ * DL_];   // conv output  [N,128] (reused [N,64])
__device__ float g_h   [(size_t)NN_ * DL_];   // segment sum  [N,128] (reused [N,64])
__device__ float g_x2  [(size_t)NN_ * DI_];   // layer-1 out  [N,64]

__device__ __forceinline__ float leaky_(float v) { return v > 0.0f ? v : 0.01f * v; }

__device__ __forceinline__ float to_tf32(float x) {
    float r;
    asm("cvt.rna.tf32.f32 %0, %1;" : "=f"(r) : "f"(x));
    return r;
}

__device__ __forceinline__ void mma_tf32(float* d, const unsigned* a, const unsigned* b) {
    asm volatile(
        "mma.sync.aligned.m16n8k8.row.col.f32.tf32.tf32.f32 "
        "{%0,%1,%2,%3}, {%4,%5,%6,%7}, {%8,%9}, {%0,%1,%2,%3};"
        : "+f"(d[0]), "+f"(d[1]), "+f"(d[2]), "+f"(d[3])
        : "r"(a[0]), "r"(a[1]), "r"(a[2]), "r"(a[3]), "r"(b[0]), "r"(b[1]));
}

// ---------------------------------------------------------------------------
// Pipelined tf32 tensor-core GEMM: C[M,BN] = op(A[M,K]) @ B
//   TRANSB=false: B is [K,BN] row-major (x @ W)
//   TRANSB=true : B is [BN,K] row-major (x @ W^T)
//   NORM: row-wise L2-normalize the output (bias applied first).
// Block tile 128 x BN, BK=16 double-buffered, 256 threads (8 warps).
// ---------------------------------------------------------------------------
template <int BN, bool TRANSB, bool NORM>
__global__ __launch_bounds__(256) void mma_gemm(
    const float* __restrict__ A, const float* __restrict__ B,
    float* __restrict__ C, int M, int K,
    const float* __restrict__ bias)
{
    constexpr int BM = 128, BK = 16;
    constexpr int WARPS_M = (BN == 128) ? 2 : 4;
    constexpr int WARPS_N = 8 / WARPS_M;
    constexpr int WM = BM / WARPS_M;
    constexpr int WN = BN / WARPS_N;
    constexpr int MT = WM / 16;
    constexpr int NT = WN / 8;

    __shared__ __align__(16) float sA[2][BM][BK + 4];
    constexpr int SB_ROWS = TRANSB ? BN : BK;
    constexpr int SB_COLS = TRANSB ? (BK + 4) : (BN + 8);
    __shared__ __align__(16) float sB[2][SB_ROWS][SB_COLS];
    __shared__ float sNorm[NORM ? BM : 1];

    const int t    = threadIdx.x;
    const int wid  = t >> 5;
    const int lane = t & 31;
    const int gid  = lane >> 2;
    const int tidg = lane & 3;
    const int wm   = (wid % WARPS_M) * WM;
    const int wn   = (wid / WARPS_M) * WN;
    const int m0   = blockIdx.x * BM;

    constexpr int A_LD = (BM * BK) / (256 * 4);
    constexpr int B_LD = (BN * BK) / (256 * 4);

    float4 aReg[A_LD], bReg[B_LD];

    float acc[MT][NT][4];
#pragma unroll
    for (int i = 0; i < MT; i++)
#pragma unroll
        for (int j = 0; j < NT; j++)
#pragma unroll
            for (int q = 0; q < 4; q++) acc[i][j][q] = 0.0f;

#define LOAD_A(K0)                                                          \
    _Pragma("unroll")                                                       \
    for (int i = 0; i < A_LD; i++) {                                        \
        int fid = t + i * 256;                                              \
        int r = fid >> 2, k4 = fid & 3;                                     \
        int row = m0 + r;                                                   \
        float4 v = make_float4(0.f, 0.f, 0.f, 0.f);                         \
        if (row < M) v = *(const float4*)&A[(size_t)row * K + (K0) + k4*4]; \
        aReg[i] = v;                                                        \
    }

#define STORE_A(BUF)                                                        \
    _Pragma("unroll")                                                       \
    for (int i = 0; i < A_LD; i++) {                                        \
        int fid = t + i * 256;                                              \
        int r = fid >> 2, k4 = fid & 3;                                     \
        float4 v = aReg[i];                                                 \
        v.x = to_tf32(v.x); v.y = to_tf32(v.y);                             \
        v.z = to_tf32(v.z); v.w = to_tf32(v.w);                             \
        *(float4*)&sA[BUF][r][k4 * 4] = v;                                  \
    }

#define LOAD_B(K0)                                                          \
    _Pragma("unroll")                                                       \
    for (int i = 0; i < B_LD; i++) {                                        \
        int fid = t + i * 256;                                              \
        if (TRANSB) {                                                       \
            int n = fid >> 2, k4 = fid & 3;                                 \
            bReg[i] = *(const float4*)&B[(size_t)n * K + (K0) + k4 * 4];    \
        } else {                                                            \
            int kk = fid / (BN / 4), n4 = fid % (BN / 4);                   \
            bReg[i] = *(const float4*)&B[(size_t)((K0) + kk) * BN + n4*4];  \
        }                                                                   \
    }

#define STORE_B(BUF)                                                        \
    _Pragma("unroll")                                                       \
    for (int i = 0; i < B_LD; i++) {                                        \
        int fid = t + i * 256;                                              \
        float4 v = bReg[i];                                                 \
        v.x = to_tf32(v.x); v.y = to_tf32(v.y);                             \
        v.z = to_tf32(v.z); v.w = to_tf32(v.w);                             \
        if (TRANSB) {                                                       \
            int n = fid >> 2, k4 = fid & 3;                                 \
            *(float4*)&sB[BUF][n][k4 * 4] = v;                              \
        } else {                                                            \
            int kk = fid / (BN / 4), n4 = fid % (BN / 4);                   \
            *(float4*)&sB[BUF][kk][n4 * 4] = v;                             \
        }                                                                   \
    }

    const int nk = K / BK;

    LOAD_A(0); LOAD_B(0);
    STORE_A(0); STORE_B(0);
    __syncthreads();

    for (int it = 0; it < nk; it++) {
        const int buf = it & 1;
        if (it + 1 < nk) { LOAD_A((it + 1) * BK); LOAD_B((it + 1) * BK); }

#pragma unroll
        for (int kk = 0; kk < BK; kk += 8) {
            unsigned afrag[MT][4];
#pragma unroll
            for (int mt = 0; mt < MT; mt++) {
                int r = wm + mt * 16 + gid;
                afrag[mt][0] = __float_as_uint(sA[buf][r][kk + tidg]);
                afrag[mt][1] = __float_as_uint(sA[buf][r + 8][kk + tidg]);
                afrag[mt][2] = __float_as_uint(sA[buf][r][kk + tidg + 4]);
                afrag[mt][3] = __float_as_uint(sA[buf][r + 8][kk + tidg + 4]);
            }
            unsigned bfrag[NT][2];
#pragma unroll
            for (int nt = 0; nt < NT; nt++) {
                int n = wn + nt * 8 + gid;
                if (TRANSB) {
                    bfrag[nt][0] = __float_as_uint(sB[buf][n][kk + tidg]);
                    bfrag[nt][1] = __float_as_uint(sB[buf][n][kk + tidg + 4]);
                } else {
                    bfrag[nt][0] = __float_as_uint(sB[buf][kk + tidg][n]);
                    bfrag[nt][1] = __float_as_uint(sB[buf][kk + tidg + 4][n]);
                }
            }
#pragma unroll
            for (int mt = 0; mt < MT; mt++)
#pragma unroll
                for (int nt = 0; nt < NT; nt++)
                    mma_tf32(acc[mt][nt], afrag[mt], bfrag[nt]);
        }

        if (it + 1 < nk) {
            STORE_A(buf ^ 1); STORE_B(buf ^ 1);
            __syncthreads();
        }
    }

    if (NORM) {
        if (t < BM) sNorm[t] = 0.0f;
        __syncthreads();
#pragma unroll
        for (int mt = 0; mt < MT; mt++)
#pragma unroll
            for (int nt = 0; nt < NT; nt++) {
                int col = wn + nt * 8 + 2 * tidg;
#pragma unroll
                for (int half = 0; half < 2; half++) {
                    int rl = wm + mt * 16 + gid + half * 8;
                    if (m0 + rl >= M) continue;
                    float v0 = acc[mt][nt][half * 2 + 0] + bias[col];
                    float v1 = acc[mt][nt][half * 2 + 1] + bias[col + 1];
                    acc[mt][nt][half * 2 + 0] = v0;
                    acc[mt][nt][half * 2 + 1] = v1;
                    atomicAdd(&sNorm[rl], v0 * v0 + v1 * v1);
                }
            }
        __syncthreads();
        if (t < BM) sNorm[t] = 1.0f / fmaxf(sqrtf(sNorm[t]), 1e-12f);
        __syncthreads();
#pragma unroll
        for (int mt = 0; mt < MT; mt++)
#pragma unroll
            for (int nt = 0; nt < NT; nt++) {
                int col = wn + nt * 8 + 2 * tidg;
#pragma unroll
                for (int half = 0; half < 2; half++) {
                    int rl = wm + mt * 16 + gid + half * 8;
                    int row = m0 + rl;
                    if (row >= M) continue;
                    float inv = sNorm[rl];
                    *(float2*)&C[(size_t)row * BN + col] = make_float2(
                        acc[mt][nt][half * 2 + 0] * inv,
                        acc[mt][nt][half * 2 + 1] * inv);
                }
            }
    } else {
#pragma unroll
        for (int mt = 0; mt < MT; mt++)
#pragma unroll
            for (int nt = 0; nt < NT; nt++) {
                int col = wn + nt * 8 + 2 * tidg;
#pragma unroll
                for (int half = 0; half < 2; half++) {
                    int row = m0 + wm + mt * 16 + gid + half * 8;
                    if (row >= M) continue;
                    *(float2*)&C[(size_t)row * BN + col] = make_float2(
                        acc[mt][nt][half * 2 + 0], acc[mt][nt][half * 2 + 1]);
                }
            }
    }
#undef LOAD_A
#undef STORE_A
#undef LOAD_B
#undef STORE_B
}

// ---------------------------------------------------------------------------
// Dual GEMM (fused lin + g per layer), BN=64, BK=8 double-buffered:
//   acc1 = A1 @ W1^T           (A1 = x)
//   acc2 = leaky(A2) @ W2^T    (A2 = h)
//   C = leaky( acc2 + b2[c] + leaky(acc1 + b1[c]) + id[row,c] )
// ---------------------------------------------------------------------------
__global__ __launch_bounds__(256) void dual_gemm(
    const float* __restrict__ A1, const float* __restrict__ A2,
    const float* __restrict__ W1, const float* __restrict__ W2,
    const float* __restrict__ b1, const float* __restrict__ b2,
    const float* __restrict__ id_emb, float* __restrict__ C,
    int M, int K)
{
    constexpr int BM = 128, BN = 64, BK = 8;
    constexpr int WM = 32, WN = 32, MT = 2, NT = 4;   // 4x2 warps

    __shared__ __align__(16) float sA1[2][BM][BK + 4];
    __shared__ __align__(16) float sA2[2][BM][BK + 4];
    __shared__ __align__(16) float sB[2][2 * BN][BK + 4];  // rows 0-63: W1, 64-127: W2

    const int t    = threadIdx.x;
    const int wid  = t >> 5;
    const int lane = t & 31;
    const int gid  = lane >> 2;
    const int tidg = lane & 3;
    const int wm   = (wid & 3) * WM;
    const int wn   = (wid >> 2) * WN;
    const int m0   = blockIdx.x * BM;

    float4 a1Reg, a2Reg, bReg;
    const int lr  = t >> 1;       // 0..127
    const int lk4 = t & 1;        // 0..1 (float4 within 8-float row chunk)

    float acc1[MT][NT][4], acc2[MT][NT][4];
#pragma unroll
    for (int i = 0; i < MT; i++)
#pragma unroll
        for (int j = 0; j < NT; j++)
#pragma unroll
            for (int q = 0; q < 4; q++) { acc1[i][j][q] = 0.f; acc2[i][j][q] = 0.f; }

#define DLOAD(K0)                                                             \
    {                                                                         \
        int row = m0 + lr;                                                    \
        a1Reg = make_float4(0.f, 0.f, 0.f, 0.f);                              \
        a2Reg = make_float4(0.f, 0.f, 0.f, 0.f);                              \
        if (row < M) {                                                        \
            a1Reg = *(const float4*)&A1[(size_t)row * K + (K0) + lk4 * 4];    \
            a2Reg = *(const float4*)&A2[(size_t)row * K + (K0) + lk4 * 4];    \
        }                                                                     \
        const float* Wp = (lr < BN) ? &W1[(size_t)lr * K]                     \
                                    : &W2[(size_t)(lr - BN) * K];             \
        bReg = *(const float4*)&Wp[(K0) + lk4 * 4];                           \
    }

#define DSTORE(BUF)                                                           \
    {                                                                         \
        float4 v = a1Reg;                                                     \
        v.x = to_tf32(v.x); v.y = to_tf32(v.y);                               \
        v.z = to_tf32(v.z); v.w = to_tf32(v.w);                               \
        *(float4*)&sA1[BUF][lr][lk4 * 4] = v;                                 \
        v = a2Reg;                                                            \
        v.x = to_tf32(leaky_(v.x)); v.y = to_tf32(leaky_(v.y));               \
        v.z = to_tf32(leaky_(v.z)); v.w = to_tf32(leaky_(v.w));               \
        *(float4*)&sA2[BUF][lr][lk4 * 4] = v;                                 \
        v = bReg;                                                             \
        v.x = to_tf32(v.x); v.y = to_tf32(v.y);                               \
        v.z = to_tf32(v.z); v.w = to_tf32(v.w);                               \
        *(float4*)&sB[BUF][lr][lk4 * 4] = v;                                  \
    }

    const int nk = K / BK;
    DLOAD(0); DSTORE(0);
    __syncthreads();

    for (int it = 0; it < nk; it++) {
        const int buf = it & 1;
        if (it + 1 < nk) DLOAD((it + 1) * BK);

        unsigned af1[MT][4], af2[MT][4];
#pragma unroll
        for (int mt = 0; mt < MT; mt++) {
            int r = wm + mt * 16 + gid;
            af1[mt][0] = __float_as_uint(sA1[buf][r][tidg]);
            af1[mt][1] = __float_as_uint(sA1[buf][r + 8][tidg]);
            af1[mt][2] = __float_as_uint(sA1[buf][r][tidg + 4]);
            af1[mt][3] = __float_as_uint(sA1[buf][r + 8][tidg + 4]);
            af2[mt][0] = __float_as_uint(sA2[buf][r][tidg]);
            af2[mt][1] = __float_as_uint(sA2[buf][r + 8][tidg]);
            af2[mt][2] = __float_as_uint(sA2[buf][r][tidg + 4]);
            af2[mt][3] = __float_as_uint(sA2[buf][r + 8][tidg + 4]);
        }
        unsigned bf1[NT][2], bf2[NT][2];
#pragma unroll
        for (int nt = 0; nt < NT; nt++) {
            int n = wn + nt * 8 + gid;
            bf1[nt][0] = __float_as_uint(sB[buf][n][tidg]);
            bf1[nt][1] = __float_as_uint(sB[buf][n][tidg + 4]);
            bf2[nt][0] = __float_as_uint(sB[buf][n + BN][tidg]);
            bf2[nt][1] = __float_as_uint(sB[buf][n + BN][tidg + 4]);
        }
#pragma unroll
        for (int mt = 0; mt < MT; mt++)
#pragma unroll
            for (int nt = 0; nt < NT; nt++) {
                mma_tf32(acc1[mt][nt], af1[mt], bf1[nt]);
                mma_tf32(acc2[mt][nt], af2[mt], bf2[nt]);
            }

        if (it + 1 < nk) {
            DSTORE(buf ^ 1);
            __syncthreads();
        }
    }

    // Epilogue: C = leaky( acc2 + b2 + leaky(acc1 + b1) + id )
#pragma unroll
    for (int mt = 0; mt < MT; mt++)
#pragma unroll
        for (int nt = 0; nt < NT; nt++) {
            int col = wn + nt * 8 + 2 * tidg;
#pragma unroll
            for (int half = 0; half < 2; half++) {
                int row = m0 + wm + mt * 16 + gid + half * 8;
                if (row >= M) continue;
                float xh0 = leaky_(acc1[mt][nt][half * 2 + 0] + b1[col])
                          + id_emb[(size_t)row * BN + col];
                float xh1 = leaky_(acc1[mt][nt][half * 2 + 1] + b1[col + 1])
                          + id_emb[(size_t)row * BN + col + 1];
                float v0 = leaky_(acc2[mt][nt][half * 2 + 0] + b2[col] + xh0);
                float v1 = leaky_(acc2[mt][nt][half * 2 + 1] + b2[col + 1] + xh1);
                *(float2*)&C[(size_t)row * BN + col] = make_float2(v0, v1);
            }
        }
#undef DLOAD
#undef DSTORE
}

// ---------------------------------------------------------------------------
// Fused copy + row-wise L2 normalize for preference rows (D=128, warp/row)
// ---------------------------------------------------------------------------
__global__ void pref_norm_kernel(const float* __restrict__ src,
                                 float* __restrict__ dst, int nrows)
{
    int warp = (blockIdx.x * blockDim.x + threadIdx.x) >> 5;
    int lane = threadIdx.x & 31;
    if (warp >= nrows) return;
    float4 v = *(const float4*)&src[(size_t)warp * 128 + lane * 4];
    float ss = v.x * v.x + v.y * v.y + v.z * v.z + v.w * v.w;
#pragma unroll
    for (int o = 16; o; o >>= 1) ss += __shfl_xor_sync(0xffffffffu, ss, o);
    float inv = 1.0f / fmaxf(sqrtf(ss), 1e-12f);
    v.x *= inv; v.y *= inv; v.z *= inv; v.w *= inv;
    *(float4*)&dst[(size_t)warp * 128 + lane * 4] = v;
}

// ---------------------------------------------------------------------------
// Edge scatter with 4-edge ILP: h[dst] += xw[src] (red.global.add.v4.f32).
// Each thread handles the q-th float4 slice of EPT=4 consecutive edges,
// giving 4 independent ld->ld->red chains per thread.
// ---------------------------------------------------------------------------
template <int D>
__global__ void scatter_kernel(const float* __restrict__ xw,
                               const int* __restrict__ ei,
                               float* __restrict__ h)
{
    constexpr int G = D / 4;        // float4 slices per row
    constexpr int EPT = 4;          // edges per thread (NE_ % EPT == 0)
    int t = blockIdx.x * blockDim.x + threadIdx.x;
    int grp = t / G;
    int q   = t % G;
    int e0  = grp * EPT;
    if (e0 >= NE_) return;

    int src[EPT], dst[EPT];
#pragma unroll
    for (int j = 0; j < EPT; j++) {
        src[j] = __ldg(&ei[e0 + j]);
        dst[j] = __ldg(&ei[NE_ + e0 + j]);
    }
    float4 v[EPT];
#pragma unroll
    for (int j = 0; j < EPT; j++)
        v[j] = *(const float4*)&xw[(size_t)src[j] * D + q * 4];
#pragma unroll
    for (int j = 0; j < EPT; j++) {
        float* hp = &h[(size_t)dst[j] * D + q * 4];
        asm volatile("red.global.add.v4.f32 [%0], {%1, %2, %3, %4};"
                     :: "l"(hp), "f"(v[j].x), "f"(v[j].y), "f"(v[j].z), "f"(v[j].w)
                     : "memory");
    }
}

// ---------------------------------------------------------------------------
extern "C" void kernel_launch(void* const* d_in, const int* in_sizes, int n_in,
                              void* d_out, int out_size)
{
    const float* features = (const float*)d_in[0];
    const float* id_emb   = (const float*)d_in[1];
    const float* pref     = (const float*)d_in[2];
    const float* mlp_w    = (const float*)d_in[3];
    const float* mlp_b    = (const float*)d_in[4];
    const float* conv1_w  = (const float*)d_in[5];
    const float* lin1_w   = (const float*)d_in[6];
    const float* lin1_b   = (const float*)d_in[7];
    const float* g1_w     = (const float*)d_in[8];
    const float* g1_b     = (const float*)d_in[9];
    const float* conv2_w  = (const float*)d_in[10];
    const float* lin2_w   = (const float*)d_in[11];
    const float* lin2_b   = (const float*)d_in[12];
    const float* g2_w     = (const float*)d_in[13];
    const float* g2_b     = (const float*)d_in[14];
    const int*   ei       = (const int*)d_in[15];
    float* out = (float*)d_out;

    float *px, *pxw, *ph, *px2;
    cudaGetSymbolAddress((void**)&px,  g_x);
    cudaGetSymbolAddress((void**)&pxw, g_xw);
    cudaGetSymbolAddress((void**)&ph,  g_h);
    cudaGetSymbolAddress((void**)&px2, g_x2);

    const int GB_N = (NN_ + 127) / 128;

    // x[:NU] = normalize(preference)
    pref_norm_kernel<<<(NU_ * 32 + 255) / 256, 256>>>(pref, px, NU_);

    // x[NU:] = normalize(features @ mlp_w^T + mlp_b)
    mma_gemm<128, true, true><<<(NI_ + 127) / 128, 256>>>(
        features, mlp_w, px + (size_t)NU_ * DL_, NI_, DF_, mlp_b);

    // ===== layer 1 =====
    mma_gemm<128, false, false><<<GB_N, 256>>>(px, conv1_w, pxw, NN_, DL_, nullptr);
    cudaMemsetAsync(ph, 0, (size_t)NN_ * DL_ * sizeof(float), 0);
    scatter_kernel<128><<<((NE_ / 4) * 32 + 255) / 256, 256>>>(pxw, ei, ph);
    dual_gemm<<<GB_N, 256>>>(px, ph, lin1_w, g1_w, lin1_b, g1_b, id_emb, px2, NN_, DL_);

    // ===== layer 2 =====
    mma_gemm<64, false, false><<<GB_N, 256>>>(px2, conv2_w, pxw, NN_, DI_, nullptr);
    cudaMemsetAsync(ph, 0, (size_t)NN_ * DI_ * sizeof(float), 0);
    scatter_kernel<64><<<((NE_ / 4) * 16 + 255) / 256, 256>>>(pxw, ei, ph);
    dual_gemm<<<GB_N, 256>>>(px2, ph, lin2_w, g2_w, lin2_b, g2_b, id_emb, out, NN_, DI_);
}

// round 5
// speedup vs baseline: 3.2129x; 1.1386x over previous
#include <cuda_runtime.h>
#include <math.h>

// Problem constants (fixed shapes per reference)
#define NU_  40000
#define NI_  60000
#define NN_  100000
#define DF_  1024
#define DL_  128
#define DI_  64
#define NE_  1600000

// Scratch buffers (device globals: allocation-guard safe)
__device__ float g_x   [(size_t)NN_ * DL_];   // normalized x [N,128]
__device__ float g_xw  [(size_t)NN_ * DL_];   // conv output  [N,128] (reused [N,64])
__device__ float g_h   [(size_t)NN_ * DL_];   // segment sum  [N,128] (reused [N,64])
__device__ float g_x2  [(size_t)NN_ * DI_];   // layer-1 out  [N,64]
// CSR build scratch
__device__ int g_cnt [NN_ + 1];
__device__ int g_offs[NN_ + 1];
__device__ int g_part[128];
__device__ int g_pos [NN_];
__device__ int g_srcs[NE_];

__device__ __forceinline__ float leaky_(float v) { return v > 0.0f ? v : 0.01f * v; }

__device__ __forceinline__ float to_tf32(float x) {
    float r;
    asm("cvt.rna.tf32.f32 %0, %1;" : "=f"(r) : "f"(x));
    return r;
}

__device__ __forceinline__ void mma_tf32(float* d, const unsigned* a, const unsigned* b) {
    asm volatile(
        "mma.sync.aligned.m16n8k8.row.col.f32.tf32.tf32.f32 "
        "{%0,%1,%2,%3}, {%4,%5,%6,%7}, {%8,%9}, {%0,%1,%2,%3};"
        : "+f"(d[0]), "+f"(d[1]), "+f"(d[2]), "+f"(d[3])
        : "r"(a[0]), "r"(a[1]), "r"(a[2]), "r"(a[3]), "r"(b[0]), "r"(b[1]));
}

// ---------------------------------------------------------------------------
// Pipelined tf32 tensor-core GEMM: C[M,BN] = op(A[M,K]) @ B
// ---------------------------------------------------------------------------
template <int BN, bool TRANSB, bool NORM>
__global__ __launch_bounds__(256) void mma_gemm(
    const float* __restrict__ A, const float* __restrict__ B,
    float* __restrict__ C, int M, int K,
    const float* __restrict__ bias)
{
    constexpr int BM = 128, BK = 16;
    constexpr int WARPS_M = (BN == 128) ? 2 : 4;
    constexpr int WARPS_N = 8 / WARPS_M;
    constexpr int WM = BM / WARPS_M;
    constexpr int WN = BN / WARPS_N;
    constexpr int MT = WM / 16;
    constexpr int NT = WN / 8;

    __shared__ __align__(16) float sA[2][BM][BK + 4];
    constexpr int SB_ROWS = TRANSB ? BN : BK;
    constexpr int SB_COLS = TRANSB ? (BK + 4) : (BN + 8);
    __shared__ __align__(16) float sB[2][SB_ROWS][SB_COLS];
    __shared__ float sNorm[NORM ? BM : 1];

    const int t    = threadIdx.x;
    const int wid  = t >> 5;
    const int lane = t & 31;
    const int gid  = lane >> 2;
    const int tidg = lane & 3;
    const int wm   = (wid % WARPS_M) * WM;
    const int wn   = (wid / WARPS_M) * WN;
    const int m0   = blockIdx.x * BM;

    constexpr int A_LD = (BM * BK) / (256 * 4);
    constexpr int B_LD = (BN * BK) / (256 * 4);

    float4 aReg[A_LD], bReg[B_LD];

    float acc[MT][NT][4];
#pragma unroll
    for (int i = 0; i < MT; i++)
#pragma unroll
        for (int j = 0; j < NT; j++)
#pragma unroll
            for (int q = 0; q < 4; q++) acc[i][j][q] = 0.0f;

#define LOAD_A(K0)                                                          \
    _Pragma("unroll")                                                       \
    for (int i = 0; i < A_LD; i++) {                                        \
        int fid = t + i * 256;                                              \
        int r = fid >> 2, k4 = fid & 3;                                     \
        int row = m0 + r;                                                   \
        float4 v = make_float4(0.f, 0.f, 0.f, 0.f);                         \
        if (row < M) v = *(const float4*)&A[(size_t)row * K + (K0) + k4*4]; \
        aReg[i] = v;                                                        \
    }

#define STORE_A(BUF)                                                        \
    _Pragma("unroll")                                                       \
    for (int i = 0; i < A_LD; i++) {                                        \
        int fid = t + i * 256;                                              \
        int r = fid >> 2, k4 = fid & 3;                                     \
        float4 v = aReg[i];                                                 \
        v.x = to_tf32(v.x); v.y = to_tf32(v.y);                             \
        v.z = to_tf32(v.z); v.w = to_tf32(v.w);                             \
        *(float4*)&sA[BUF][r][k4 * 4] = v;                                  \
    }

#define LOAD_B(K0)                                                          \
    _Pragma("unroll")                                                       \
    for (int i = 0; i < B_LD; i++) {                                        \
        int fid = t + i * 256;                                              \
        if (TRANSB) {                                                       \
            int n = fid >> 2, k4 = fid & 3;                                 \
            bReg[i] = *(const float4*)&B[(size_t)n * K + (K0) + k4 * 4];    \
        } else {                                                            \
            int kk = fid / (BN / 4), n4 = fid % (BN / 4);                   \
            bReg[i] = *(const float4*)&B[(size_t)((K0) + kk) * BN + n4*4];  \
        }                                                                   \
    }

#define STORE_B(BUF)                                                        \
    _Pragma("unroll")                                                       \
    for (int i = 0; i < B_LD; i++) {                                        \
        int fid = t + i * 256;                                              \
        float4 v = bReg[i];                                                 \
        v.x = to_tf32(v.x); v.y = to_tf32(v.y);                             \
        v.z = to_tf32(v.z); v.w = to_tf32(v.w);                             \
        if (TRANSB) {                                                       \
            int n = fid >> 2, k4 = fid & 3;                                 \
            *(float4*)&sB[BUF][n][k4 * 4] = v;                              \
        } else {                                                            \
            int kk = fid / (BN / 4), n4 = fid % (BN / 4);                   \
            *(float4*)&sB[BUF][kk][n4 * 4] = v;                             \
        }                                                                   \
    }

    const int nk = K / BK;

    LOAD_A(0); LOAD_B(0);
    STORE_A(0); STORE_B(0);
    __syncthreads();

    for (int it = 0; it < nk; it++) {
        const int buf = it & 1;
        if (it + 1 < nk) { LOAD_A((it + 1) * BK); LOAD_B((it + 1) * BK); }

#pragma unroll
        for (int kk = 0; kk < BK; kk += 8) {
            unsigned afrag[MT][4];
#pragma unroll
            for (int mt = 0; mt < MT; mt++) {
                int r = wm + mt * 16 + gid;
                afrag[mt][0] = __float_as_uint(sA[buf][r][kk + tidg]);
                afrag[mt][1] = __float_as_uint(sA[buf][r + 8][kk + tidg]);
                afrag[mt][2] = __float_as_uint(sA[buf][r][kk + tidg + 4]);
                afrag[mt][3] = __float_as_uint(sA[buf][r + 8][kk + tidg + 4]);
            }
            unsigned bfrag[NT][2];
#pragma unroll
            for (int nt = 0; nt < NT; nt++) {
                int n = wn + nt * 8 + gid;
                if (TRANSB) {
                    bfrag[nt][0] = __float_as_uint(sB[buf][n][kk + tidg]);
                    bfrag[nt][1] = __float_as_uint(sB[buf][n][kk + tidg + 4]);
                } else {
                    bfrag[nt][0] = __float_as_uint(sB[buf][kk + tidg][n]);
                    bfrag[nt][1] = __float_as_uint(sB[buf][kk + tidg + 4][n]);
                }
            }
#pragma unroll
            for (int mt = 0; mt < MT; mt++)
#pragma unroll
                for (int nt = 0; nt < NT; nt++)
                    mma_tf32(acc[mt][nt], afrag[mt], bfrag[nt]);
        }

        if (it + 1 < nk) {
            STORE_A(buf ^ 1); STORE_B(buf ^ 1);
            __syncthreads();
        }
    }

    if (NORM) {
        if (t < BM) sNorm[t] = 0.0f;
        __syncthreads();
#pragma unroll
        for (int mt = 0; mt < MT; mt++)
#pragma unroll
            for (int nt = 0; nt < NT; nt++) {
                int col = wn + nt * 8 + 2 * tidg;
#pragma unroll
                for (int half = 0; half < 2; half++) {
                    int rl = wm + mt * 16 + gid + half * 8;
                    if (m0 + rl >= M) continue;
                    float v0 = acc[mt][nt][half * 2 + 0] + bias[col];
                    float v1 = acc[mt][nt][half * 2 + 1] + bias[col + 1];
                    acc[mt][nt][half * 2 + 0] = v0;
                    acc[mt][nt][half * 2 + 1] = v1;
                    atomicAdd(&sNorm[rl], v0 * v0 + v1 * v1);
                }
            }
        __syncthreads();
        if (t < BM) sNorm[t] = 1.0f / fmaxf(sqrtf(sNorm[t]), 1e-12f);
        __syncthreads();
#pragma unroll
        for (int mt = 0; mt < MT; mt++)
#pragma unroll
            for (int nt = 0; nt < NT; nt++) {
                int col = wn + nt * 8 + 2 * tidg;
#pragma unroll
                for (int half = 0; half < 2; half++) {
                    int rl = wm + mt * 16 + gid + half * 8;
                    int row = m0 + rl;
                    if (row >= M) continue;
                    float inv = sNorm[rl];
                    *(float2*)&C[(size_t)row * BN + col] = make_float2(
                        acc[mt][nt][half * 2 + 0] * inv,
                        acc[mt][nt][half * 2 + 1] * inv);
                }
            }
    } else {
#pragma unroll
        for (int mt = 0; mt < MT; mt++)
#pragma unroll
            for (int nt = 0; nt < NT; nt++) {
                int col = wn + nt * 8 + 2 * tidg;
#pragma unroll
                for (int half = 0; half < 2; half++) {
                    int row = m0 + wm + mt * 16 + gid + half * 8;
                    if (row >= M) continue;
                    *(float2*)&C[(size_t)row * BN + col] = make_float2(
                        acc[mt][nt][half * 2 + 0], acc[mt][nt][half * 2 + 1]);
                }
            }
    }
#undef LOAD_A
#undef STORE_A
#undef LOAD_B
#undef STORE_B
}

// ---------------------------------------------------------------------------
// Dual GEMM (fused lin + g per layer), BN=64, BK=8 double-buffered:
//   C = leaky( (leaky(A2) @ W2^T) + b2 + leaky(A1 @ W1^T + b1) + id )
// ---------------------------------------------------------------------------
__global__ __launch_bounds__(256) void dual_gemm(
    const float* __restrict__ A1, const float* __restrict__ A2,
    const float* __restrict__ W1, const float* __restrict__ W2,
    const float* __restrict__ b1, const float* __restrict__ b2,
    const float* __restrict__ id_emb, float* __restrict__ C,
    int M, int K)
{
    constexpr int BM = 128, BN = 64, BK = 8;
    constexpr int WM = 32, WN = 32, MT = 2, NT = 4;

    __shared__ __align__(16) float sA1[2][BM][BK + 4];
    __shared__ __align__(16) float sA2[2][BM][BK + 4];
    __shared__ __align__(16) float sB[2][2 * BN][BK + 4];

    const int t    = threadIdx.x;
    const int wid  = t >> 5;
    const int lane = t & 31;
    const int gid  = lane >> 2;
    const int tidg = lane & 3;
    const int wm   = (wid & 3) * WM;
    const int wn   = (wid >> 2) * WN;
    const int m0   = blockIdx.x * BM;

    float4 a1Reg, a2Reg, bReg;
    const int lr  = t >> 1;
    const int lk4 = t & 1;

    float acc1[MT][NT][4], acc2[MT][NT][4];
#pragma unroll
    for (int i = 0; i < MT; i++)
#pragma unroll
        for (int j = 0; j < NT; j++)
#pragma unroll
            for (int q = 0; q < 4; q++) { acc1[i][j][q] = 0.f; acc2[i][j][q] = 0.f; }

#define DLOAD(K0)                                                             \
    {                                                                         \
        int row = m0 + lr;                                                    \
        a1Reg = make_float4(0.f, 0.f, 0.f, 0.f);                              \
        a2Reg = make_float4(0.f, 0.f, 0.f, 0.f);                              \
        if (row < M) {                                                        \
            a1Reg = *(const float4*)&A1[(size_t)row * K + (K0) + lk4 * 4];    \
            a2Reg = *(const float4*)&A2[(size_t)row * K + (K0) + lk4 * 4];    \
        }                                                                     \
        const float* Wp = (lr < BN) ? &W1[(size_t)lr * K]                     \
                                    : &W2[(size_t)(lr - BN) * K];             \
        bReg = *(const float4*)&Wp[(K0) + lk4 * 4];                           \
    }

#define DSTORE(BUF)                                                           \
    {                                                                         \
        float4 v = a1Reg;                                                     \
        v.x = to_tf32(v.x); v.y = to_tf32(v.y);                               \
        v.z = to_tf32(v.z); v.w = to_tf32(v.w);                               \
        *(float4*)&sA1[BUF][lr][lk4 * 4] = v;                                 \
        v = a2Reg;                                                            \
        v.x = to_tf32(leaky_(v.x)); v.y = to_tf32(leaky_(v.y));               \
        v.z = to_tf32(leaky_(v.z)); v.w = to_tf32(leaky_(v.w));               \
        *(float4*)&sA2[BUF][lr][lk4 * 4] = v;                                 \
        v = bReg;                                                             \
        v.x = to_tf32(v.x); v.y = to_tf32(v.y);                               \
        v.z = to_tf32(v.z); v.w = to_tf32(v.w);                               \
        *(float4*)&sB[BUF][lr][lk4 * 4] = v;                                  \
    }

    const int nk = K / BK;
    DLOAD(0); DSTORE(0);
    __syncthreads();

    for (int it = 0; it < nk; it++) {
        const int buf = it & 1;
        if (it + 1 < nk) DLOAD((it + 1) * BK);

        unsigned af1[MT][4], af2[MT][4];
#pragma unroll
        for (int mt = 0; mt < MT; mt++) {
            int r = wm + mt * 16 + gid;
            af1[mt][0] = __float_as_uint(sA1[buf][r][tidg]);
            af1[mt][1] = __float_as_uint(sA1[buf][r + 8][tidg]);
            af1[mt][2] = __float_as_uint(sA1[buf][r][tidg + 4]);
            af1[mt][3] = __float_as_uint(sA1[buf][r + 8][tidg + 4]);
            af2[mt][0] = __float_as_uint(sA2[buf][r][tidg]);
            af2[mt][1] = __float_as_uint(sA2[buf][r + 8][tidg]);
            af2[mt][2] = __float_as_uint(sA2[buf][r][tidg + 4]);
            af2[mt][3] = __float_as_uint(sA2[buf][r + 8][tidg + 4]);
        }
        unsigned bf1[NT][2], bf2[NT][2];
#pragma unroll
        for (int nt = 0; nt < NT; nt++) {
            int n = wn + nt * 8 + gid;
            bf1[nt][0] = __float_as_uint(sB[buf][n][tidg]);
            bf1[nt][1] = __float_as_uint(sB[buf][n][tidg + 4]);
            bf2[nt][0] = __float_as_uint(sB[buf][n + BN][tidg]);
            bf2[nt][1] = __float_as_uint(sB[buf][n + BN][tidg + 4]);
        }
#pragma unroll
        for (int mt = 0; mt < MT; mt++)
#pragma unroll
            for (int nt = 0; nt < NT; nt++) {
                mma_tf32(acc1[mt][nt], af1[mt], bf1[nt]);
                mma_tf32(acc2[mt][nt], af2[mt], bf2[nt]);
            }

        if (it + 1 < nk) {
            DSTORE(buf ^ 1);
            __syncthreads();
        }
    }

#pragma unroll
    for (int mt = 0; mt < MT; mt++)
#pragma unroll
        for (int nt = 0; nt < NT; nt++) {
            int col = wn + nt * 8 + 2 * tidg;
#pragma unroll
            for (int half = 0; half < 2; half++) {
                int row = m0 + wm + mt * 16 + gid + half * 8;
                if (row >= M) continue;
                float xh0 = leaky_(acc1[mt][nt][half * 2 + 0] + b1[col])
                          + id_emb[(size_t)row * BN + col];
                float xh1 = leaky_(acc1[mt][nt][half * 2 + 1] + b1[col + 1])
                          + id_emb[(size_t)row * BN + col + 1];
                float v0 = leaky_(acc2[mt][nt][half * 2 + 0] + b2[col] + xh0);
                float v1 = leaky_(acc2[mt][nt][half * 2 + 1] + b2[col + 1] + xh1);
                *(float2*)&C[(size_t)row * BN + col] = make_float2(v0, v1);
            }
        }
#undef DLOAD
#undef DSTORE
}

// ---------------------------------------------------------------------------
// Fused copy + row-wise L2 normalize for preference rows (D=128, warp/row)
// ---------------------------------------------------------------------------
__global__ void pref_norm_kernel(const float* __restrict__ src,
                                 float* __restrict__ dst, int nrows)
{
    int warp = (blockIdx.x * blockDim.x + threadIdx.x) >> 5;
    int lane = threadIdx.x & 31;
    if (warp >= nrows) return;
    float4 v = *(const float4*)&src[(size_t)warp * 128 + lane * 4];
    float ss = v.x * v.x + v.y * v.y + v.z * v.z + v.w * v.w;
#pragma unroll
    for (int o = 16; o; o >>= 1) ss += __shfl_xor_sync(0xffffffffu, ss, o);
    float inv = 1.0f / fmaxf(sqrtf(ss), 1e-12f);
    v.x *= inv; v.y *= inv; v.z *= inv; v.w *= inv;
    *(float4*)&dst[(size_t)warp * 128 + lane * 4] = v;
}

// ---------------------------------------------------------------------------
// CSR build: histogram of dst, 3-phase exclusive scan, src reorder by dst
// ---------------------------------------------------------------------------
__global__ void hist_kernel(const int* __restrict__ ei, int* __restrict__ cnt)
{
    int e = blockIdx.x * blockDim.x + threadIdx.x;
    if (e < NE_) atomicAdd(&cnt[__ldg(&ei[NE_ + e])], 1);
}

__global__ void scan1_kernel(const int* __restrict__ in, int* __restrict__ out,
                             int* __restrict__ part, int n)
{
    __shared__ int s[1024];
    int i = blockIdx.x * 1024 + threadIdx.x;
    int v = (i < n) ? in[i] : 0;
    s[threadIdx.x] = v;
    __syncthreads();
#pragma unroll
    for (int o = 1; o < 1024; o <<= 1) {
        int y = (threadIdx.x >= o) ? s[threadIdx.x - o] : 0;
        __syncthreads();
        s[threadIdx.x] += y;
        __syncthreads();
    }
    if (i < n) out[i] = s[threadIdx.x] - v;     // exclusive
    if (threadIdx.x == 1023) part[blockIdx.x] = s[1023];
}

__global__ void scan2_kernel(int* __restrict__ part, int nb)
{
    if (threadIdx.x == 0 && blockIdx.x == 0) {
        int run = 0;
        for (int i = 0; i < nb; i++) { int v = part[i]; part[i] = run; run += v; }
    }
}

__global__ void scan3_kernel(int* __restrict__ out, const int* __restrict__ part, int n)
{
    int i = blockIdx.x * 1024 + threadIdx.x;
    if (i < n) out[i] += part[blockIdx.x];
}

__global__ void reorder_kernel(const int* __restrict__ ei, int* __restrict__ pos,
                               int* __restrict__ srcs)
{
    int e = blockIdx.x * blockDim.x + threadIdx.x;
    if (e >= NE_) return;
    int d = __ldg(&ei[NE_ + e]);
    int idx = atomicAdd(&pos[d], 1);
    srcs[idx] = __ldg(&ei[e]);
}

// ---------------------------------------------------------------------------
// Atomic-free segmented scatter: h[d] = sum_{e: dst=d} xw[srcs[e]]
// D=128: warp per node (32 float4 lanes). D=64: half-warp per node.
// ---------------------------------------------------------------------------
template <int D>
__global__ void seg_scatter(const float* __restrict__ xw,
                            const int* __restrict__ offs,
                            const int* __restrict__ srcs,
                            float* __restrict__ h)
{
    constexpr int G = D / 4;
    int gt   = blockIdx.x * blockDim.x + threadIdx.x;
    int node = gt / G;
    int q    = threadIdx.x % G;
    if (node >= NN_) return;

    int s   = __ldg(&offs[node]);
    int end = __ldg(&offs[node + 1]);

    float4 a0 = make_float4(0.f, 0.f, 0.f, 0.f);
    float4 a1 = make_float4(0.f, 0.f, 0.f, 0.f);
    float4 a2 = make_float4(0.f, 0.f, 0.f, 0.f);
    float4 a3 = make_float4(0.f, 0.f, 0.f, 0.f);

    int i = s;
    for (; i + 3 < end; i += 4) {
        int s0 = __ldg(&srcs[i + 0]);
        int s1 = __ldg(&srcs[i + 1]);
        int s2 = __ldg(&srcs[i + 2]);
        int s3 = __ldg(&srcs[i + 3]);
        float4 v0 = *(const float4*)&xw[(size_t)s0 * D + q * 4];
        float4 v1 = *(const float4*)&xw[(size_t)s1 * D + q * 4];
        float4 v2 = *(const float4*)&xw[(size_t)s2 * D + q * 4];
        float4 v3 = *(const float4*)&xw[(size_t)s3 * D + q * 4];
        a0.x += v0.x; a0.y += v0.y; a0.z += v0.z; a0.w += v0.w;
        a1.x += v1.x; a1.y += v1.y; a1.z += v1.z; a1.w += v1.w;
        a2.x += v2.x; a2.y += v2.y; a2.z += v2.z; a2.w += v2.w;
        a3.x += v3.x; a3.y += v3.y; a3.z += v3.z; a3.w += v3.w;
    }
    for (; i < end; i++) {
        int s0 = __ldg(&srcs[i]);
        float4 v0 = *(const float4*)&xw[(size_t)s0 * D + q * 4];
        a0.x += v0.x; a0.y += v0.y; a0.z += v0.z; a0.w += v0.w;
    }
    float4 r;
    r.x = (a0.x + a1.x) + (a2.x + a3.x);
    r.y = (a0.y + a1.y) + (a2.y + a3.y);
    r.z = (a0.z + a1.z) + (a2.z + a3.z);
    r.w = (a0.w + a1.w) + (a2.w + a3.w);
    *(float4*)&h[(size_t)node * D + q * 4] = r;
}

// ---------------------------------------------------------------------------
extern "C" void kernel_launch(void* const* d_in, const int* in_sizes, int n_in,
                              void* d_out, int out_size)
{
    const float* features = (const float*)d_in[0];
    const float* id_emb   = (const float*)d_in[1];
    const float* pref     = (const float*)d_in[2];
    const float* mlp_w    = (const float*)d_in[3];
    const float* mlp_b    = (const float*)d_in[4];
    const float* conv1_w  = (const float*)d_in[5];
    const float* lin1_w   = (const float*)d_in[6];
    const float* lin1_b   = (const float*)d_in[7];
    const float* g1_w     = (const float*)d_in[8];
    const float* g1_b     = (const float*)d_in[9];
    const float* conv2_w  = (const float*)d_in[10];
    const float* lin2_w   = (const float*)d_in[11];
    const float* lin2_b   = (const float*)d_in[12];
    const float* g2_w     = (const float*)d_in[13];
    const float* g2_b     = (const float*)d_in[14];
    const int*   ei       = (const int*)d_in[15];
    float* out = (float*)d_out;

    float *px, *pxw, *ph, *px2;
    int *pcnt, *poffs, *ppart, *ppos, *psrcs;
    cudaGetSymbolAddress((void**)&px,    g_x);
    cudaGetSymbolAddress((void**)&pxw,   g_xw);
    cudaGetSymbolAddress((void**)&ph,    g_h);
    cudaGetSymbolAddress((void**)&px2,   g_x2);
    cudaGetSymbolAddress((void**)&pcnt,  g_cnt);
    cudaGetSymbolAddress((void**)&poffs, g_offs);
    cudaGetSymbolAddress((void**)&ppart, g_part);
    cudaGetSymbolAddress((void**)&ppos,  g_pos);
    cudaGetSymbolAddress((void**)&psrcs, g_srcs);

    const int GB_N   = (NN_ + 127) / 128;
    const int NSCAN  = NN_ + 1;
    const int NBLK   = (NSCAN + 1023) / 1024;   // 98

    // ---- CSR build (independent of feature pipeline; issued first) ----
    cudaMemsetAsync(pcnt, 0, NSCAN * sizeof(int), 0);
    hist_kernel<<<(NE_ + 255) / 256, 256>>>(ei, pcnt);
    scan1_kernel<<<NBLK, 1024>>>(pcnt, poffs, ppart, NSCAN);
    scan2_kernel<<<1, 32>>>(ppart, NBLK);
    scan3_kernel<<<NBLK, 1024>>>(poffs, ppart, NSCAN);
    cudaMemcpyAsync(ppos, poffs, NN_ * sizeof(int), cudaMemcpyDeviceToDevice, 0);
    reorder_kernel<<<(NE_ + 255) / 256, 256>>>(ei, ppos, psrcs);

    // ---- feature pipeline ----
    pref_norm_kernel<<<(NU_ * 32 + 255) / 256, 256>>>(pref, px, NU_);
    mma_gemm<128, true, true><<<(NI_ + 127) / 128, 256>>>(
        features, mlp_w, px + (size_t)NU_ * DL_, NI_, DF_, mlp_b);

    // ===== layer 1 =====
    mma_gemm<128, false, false><<<GB_N, 256>>>(px, conv1_w, pxw, NN_, DL_, nullptr);
    seg_scatter<128><<<(NN_ * 32 + 255) / 256, 256>>>(pxw, poffs, psrcs, ph);
    dual_gemm<<<GB_N, 256>>>(px, ph, lin1_w, g1_w, lin1_b, g1_b, id_emb, px2, NN_, DL_);

    // ===== layer 2 =====
    mma_gemm<64, false, false><<<GB_N, 256>>>(px2, conv2_w, pxw, NN_, DI_, nullptr);
    seg_scatter<64><<<(NN_ * 16 + 255) / 256, 256>>>(pxw, poffs, psrcs, ph);
    dual_gemm<<<GB_N, 256>>>(px2, ph, lin2_w, g2_w, lin2_b, g2_b, id_emb, out, NN_, DI_);
}

// round 6
// speedup vs baseline: 3.7038x; 1.1528x over previous
#include <cuda_runtime.h>
#include <cuda_bf16.h>
#include <math.h>

// Problem constants (fixed shapes per reference)
#define NU_  40000
#define NI_  60000
#define NN_  100000
#define DF_  1024
#define DL_  128
#define DI_  64
#define NE_  1600000

// Scratch buffers (device globals: allocation-guard safe)
__device__ float g_x [(size_t)NN_ * DL_];            // normalized x [N,128]
__device__ __nv_bfloat16 g_xw[(size_t)NN_ * DL_];    // conv output (bf16)
__device__ float g_h [(size_t)NN_ * DL_];            // segment sum
__device__ float g_x2[(size_t)NN_ * DI_];            // layer-1 out [N,64]
// CSR build scratch
__device__ int g_cnt [NN_ + 1];
__device__ int g_offs[NN_ + 1];
__device__ int g_part[128];
__device__ int g_pos [NN_];
__device__ int g_srcs[NE_];

__device__ __forceinline__ float leaky_(float v) { return v > 0.0f ? v : 0.01f * v; }

__device__ __forceinline__ float to_tf32(float x) {
    float r;
    asm("cvt.rna.tf32.f32 %0, %1;" : "=f"(r) : "f"(x));
    return r;
}

__device__ __forceinline__ void mma_tf32(float* d, const unsigned* a, const unsigned* b) {
    asm volatile(
        "mma.sync.aligned.m16n8k8.row.col.f32.tf32.tf32.f32 "
        "{%0,%1,%2,%3}, {%4,%5,%6,%7}, {%8,%9}, {%0,%1,%2,%3};"
        : "+f"(d[0]), "+f"(d[1]), "+f"(d[2]), "+f"(d[3])
        : "r"(a[0]), "r"(a[1]), "r"(a[2]), "r"(a[3]), "r"(b[0]), "r"(b[1]));
}

// ---------------------------------------------------------------------------
// Pipelined tf32 tensor-core GEMM: C[M,BN] = op(A[M,K]) @ B
//   OUTBF16: store output as bf16 (conv path); else fp32.
//   NORM: row-wise L2-normalize output (bias added first; fp32 out only).
// ---------------------------------------------------------------------------
template <int BN, bool TRANSB, bool NORM, bool OUTBF16>
__global__ __launch_bounds__(256) void mma_gemm(
    const float* __restrict__ A, const float* __restrict__ B,
    void* __restrict__ Cv, int M, int K,
    const float* __restrict__ bias)
{
    constexpr int BM = 128, BK = 16;
    constexpr int WARPS_M = (BN == 128) ? 2 : 4;
    constexpr int WARPS_N = 8 / WARPS_M;
    constexpr int WM = BM / WARPS_M;
    constexpr int WN = BN / WARPS_N;
    constexpr int MT = WM / 16;
    constexpr int NT = WN / 8;

    __shared__ __align__(16) float sA[2][BM][BK + 4];
    constexpr int SB_ROWS = TRANSB ? BN : BK;
    constexpr int SB_COLS = TRANSB ? (BK + 4) : (BN + 8);
    __shared__ __align__(16) float sB[2][SB_ROWS][SB_COLS];
    __shared__ float sNorm[NORM ? BM : 1];

    const int t    = threadIdx.x;
    const int wid  = t >> 5;
    const int lane = t & 31;
    const int gid  = lane >> 2;
    const int tidg = lane & 3;
    const int wm   = (wid % WARPS_M) * WM;
    const int wn   = (wid / WARPS_M) * WN;
    const int m0   = blockIdx.x * BM;

    constexpr int A_LD = (BM * BK) / (256 * 4);
    constexpr int B_LD = (BN * BK) / (256 * 4);

    float4 aReg[A_LD], bReg[B_LD];

    float acc[MT][NT][4];
#pragma unroll
    for (int i = 0; i < MT; i++)
#pragma unroll
        for (int j = 0; j < NT; j++)
#pragma unroll
            for (int q = 0; q < 4; q++) acc[i][j][q] = 0.0f;

#define LOAD_A(K0)                                                          \
    _Pragma("unroll")                                                       \
    for (int i = 0; i < A_LD; i++) {                                        \
        int fid = t + i * 256;                                              \
        int r = fid >> 2, k4 = fid & 3;                                     \
        int row = m0 + r;                                                   \
        float4 v = make_float4(0.f, 0.f, 0.f, 0.f);                         \
        if (row < M) v = *(const float4*)&A[(size_t)row * K + (K0) + k4*4]; \
        aReg[i] = v;                                                        \
    }

#define STORE_A(BUF)                                                        \
    _Pragma("unroll")                                                       \
    for (int i = 0; i < A_LD; i++) {                                        \
        int fid = t + i * 256;                                              \
        int r = fid >> 2, k4 = fid & 3;                                     \
        float4 v = aReg[i];                                                 \
        v.x = to_tf32(v.x); v.y = to_tf32(v.y);                             \
        v.z = to_tf32(v.z); v.w = to_tf32(v.w);                             \
        *(float4*)&sA[BUF][r][k4 * 4] = v;                                  \
    }

#define LOAD_B(K0)                                                          \
    _Pragma("unroll")                                                       \
    for (int i = 0; i < B_LD; i++) {                                        \
        int fid = t + i * 256;                                              \
        if (TRANSB) {                                                       \
            int n = fid >> 2, k4 = fid & 3;                                 \
            bReg[i] = *(const float4*)&B[(size_t)n * K + (K0) + k4 * 4];    \
        } else {                                                            \
            int kk = fid / (BN / 4), n4 = fid % (BN / 4);                   \
            bReg[i] = *(const float4*)&B[(size_t)((K0) + kk) * BN + n4*4];  \
        }                                                                   \
    }

#define STORE_B(BUF)                                                        \
    _Pragma("unroll")                                                       \
    for (int i = 0; i < B_LD; i++) {                                        \
        int fid = t + i * 256;                                              \
        float4 v = bReg[i];                                                 \
        v.x = to_tf32(v.x); v.y = to_tf32(v.y);                             \
        v.z = to_tf32(v.z); v.w = to_tf32(v.w);                             \
        if (TRANSB) {                                                       \
            int n = fid >> 2, k4 = fid & 3;                                 \
            *(float4*)&sB[BUF][n][k4 * 4] = v;                              \
        } else {                                                            \
            int kk = fid / (BN / 4), n4 = fid % (BN / 4);                   \
            *(float4*)&sB[BUF][kk][n4 * 4] = v;                             \
        }                                                                   \
    }

    const int nk = K / BK;

    LOAD_A(0); LOAD_B(0);
    STORE_A(0); STORE_B(0);
    __syncthreads();

    for (int it = 0; it < nk; it++) {
        const int buf = it & 1;
        if (it + 1 < nk) { LOAD_A((it + 1) * BK); LOAD_B((it + 1) * BK); }

#pragma unroll
        for (int kk = 0; kk < BK; kk += 8) {
            unsigned afrag[MT][4];
#pragma unroll
            for (int mt = 0; mt < MT; mt++) {
                int r = wm + mt * 16 + gid;
                afrag[mt][0] = __float_as_uint(sA[buf][r][kk + tidg]);
                afrag[mt][1] = __float_as_uint(sA[buf][r + 8][kk + tidg]);
                afrag[mt][2] = __float_as_uint(sA[buf][r][kk + tidg + 4]);
                afrag[mt][3] = __float_as_uint(sA[buf][r + 8][kk + tidg + 4]);
            }
            unsigned bfrag[NT][2];
#pragma unroll
            for (int nt = 0; nt < NT; nt++) {
                int n = wn + nt * 8 + gid;
                if (TRANSB) {
                    bfrag[nt][0] = __float_as_uint(sB[buf][n][kk + tidg]);
                    bfrag[nt][1] = __float_as_uint(sB[buf][n][kk + tidg + 4]);
                } else {
                    bfrag[nt][0] = __float_as_uint(sB[buf][kk + tidg][n]);
                    bfrag[nt][1] = __float_as_uint(sB[buf][kk + tidg + 4][n]);
                }
            }
#pragma unroll
            for (int mt = 0; mt < MT; mt++)
#pragma unroll
                for (int nt = 0; nt < NT; nt++)
                    mma_tf32(acc[mt][nt], afrag[mt], bfrag[nt]);
        }

        if (it + 1 < nk) {
            STORE_A(buf ^ 1); STORE_B(buf ^ 1);
            __syncthreads();
        }
    }

    if (NORM) {
        float* C = (float*)Cv;
        if (t < BM) sNorm[t] = 0.0f;
        __syncthreads();
#pragma unroll
        for (int mt = 0; mt < MT; mt++)
#pragma unroll
            for (int nt = 0; nt < NT; nt++) {
                int col = wn + nt * 8 + 2 * tidg;
#pragma unroll
                for (int half = 0; half < 2; half++) {
                    int rl = wm + mt * 16 + gid + half * 8;
                    if (m0 + rl >= M) continue;
                    float v0 = acc[mt][nt][half * 2 + 0] + bias[col];
                    float v1 = acc[mt][nt][half * 2 + 1] + bias[col + 1];
                    acc[mt][nt][half * 2 + 0] = v0;
                    acc[mt][nt][half * 2 + 1] = v1;
                    atomicAdd(&sNorm[rl], v0 * v0 + v1 * v1);
                }
            }
        __syncthreads();
        if (t < BM) sNorm[t] = 1.0f / fmaxf(sqrtf(sNorm[t]), 1e-12f);
        __syncthreads();
#pragma unroll
        for (int mt = 0; mt < MT; mt++)
#pragma unroll
            for (int nt = 0; nt < NT; nt++) {
                int col = wn + nt * 8 + 2 * tidg;
#pragma unroll
                for (int half = 0; half < 2; half++) {
                    int rl = wm + mt * 16 + gid + half * 8;
                    int row = m0 + rl;
                    if (row >= M) continue;
                    float inv = sNorm[rl];
                    *(float2*)&C[(size_t)row * BN + col] = make_float2(
                        acc[mt][nt][half * 2 + 0] * inv,
                        acc[mt][nt][half * 2 + 1] * inv);
                }
            }
    } else {
#pragma unroll
        for (int mt = 0; mt < MT; mt++)
#pragma unroll
            for (int nt = 0; nt < NT; nt++) {
                int col = wn + nt * 8 + 2 * tidg;
#pragma unroll
                for (int half = 0; half < 2; half++) {
                    int row = m0 + wm + mt * 16 + gid + half * 8;
                    if (row >= M) continue;
                    float v0 = acc[mt][nt][half * 2 + 0];
                    float v1 = acc[mt][nt][half * 2 + 1];
                    if (OUTBF16) {
                        __nv_bfloat16* C = (__nv_bfloat16*)Cv;
                        *(__nv_bfloat162*)&C[(size_t)row * BN + col] =
                            __floats2bfloat162_rn(v0, v1);
                    } else {
                        float* C = (float*)Cv;
                        *(float2*)&C[(size_t)row * BN + col] = make_float2(v0, v1);
                    }
                }
            }
    }
#undef LOAD_A
#undef STORE_A
#undef LOAD_B
#undef STORE_B
}

// ---------------------------------------------------------------------------
// Dual GEMM (fused lin + g per layer), BN=64, BK=8 double-buffered:
//   C = leaky( (leaky(A2) @ W2^T) + b2 + leaky(A1 @ W1^T + b1) + id )
// ---------------------------------------------------------------------------
__global__ __launch_bounds__(256) void dual_gemm(
    const float* __restrict__ A1, const float* __restrict__ A2,
    const float* __restrict__ W1, const float* __restrict__ W2,
    const float* __restrict__ b1, const float* __restrict__ b2,
    const float* __restrict__ id_emb, float* __restrict__ C,
    int M, int K)
{
    constexpr int BM = 128, BN = 64, BK = 8;
    constexpr int WM = 32, WN = 32, MT = 2, NT = 4;

    __shared__ __align__(16) float sA1[2][BM][BK + 4];
    __shared__ __align__(16) float sA2[2][BM][BK + 4];
    __shared__ __align__(16) float sB[2][2 * BN][BK + 4];

    const int t    = threadIdx.x;
    const int wid  = t >> 5;
    const int lane = t & 31;
    const int gid  = lane >> 2;
    const int tidg = lane & 3;
    const int wm   = (wid & 3) * WM;
    const int wn   = (wid >> 2) * WN;
    const int m0   = blockIdx.x * BM;

    float4 a1Reg, a2Reg, bReg;
    const int lr  = t >> 1;
    const int lk4 = t & 1;

    float acc1[MT][NT][4], acc2[MT][NT][4];
#pragma unroll
    for (int i = 0; i < MT; i++)
#pragma unroll
        for (int j = 0; j < NT; j++)
#pragma unroll
            for (int q = 0; q < 4; q++) { acc1[i][j][q] = 0.f; acc2[i][j][q] = 0.f; }

#define DLOAD(K0)                                                             \
    {                                                                         \
        int row = m0 + lr;                                                    \
        a1Reg = make_float4(0.f, 0.f, 0.f, 0.f);                              \
        a2Reg = make_float4(0.f, 0.f, 0.f, 0.f);                              \
        if (row < M) {                                                        \
            a1Reg = *(const float4*)&A1[(size_t)row * K + (K0) + lk4 * 4];    \
            a2Reg = *(const float4*)&A2[(size_t)row * K + (K0) + lk4 * 4];    \
        }                                                                     \
        const float* Wp = (lr < BN) ? &W1[(size_t)lr * K]                     \
                                    : &W2[(size_t)(lr - BN) * K];             \
        bReg = *(const float4*)&Wp[(K0) + lk4 * 4];                           \
    }

#define DSTORE(BUF)                                                           \
    {                                                                         \
        float4 v = a1Reg;                                                     \
        v.x = to_tf32(v.x); v.y = to_tf32(v.y);                               \
        v.z = to_tf32(v.z); v.w = to_tf32(v.w);                               \
        *(float4*)&sA1[BUF][lr][lk4 * 4] = v;                                 \
        v = a2Reg;                                                            \
        v.x = to_tf32(leaky_(v.x)); v.y = to_tf32(leaky_(v.y));               \
        v.z = to_tf32(leaky_(v.z)); v.w = to_tf32(leaky_(v.w));               \
        *(float4*)&sA2[BUF][lr][lk4 * 4] = v;                                 \
        v = bReg;                                                             \
        v.x = to_tf32(v.x); v.y = to_tf32(v.y);                               \
        v.z = to_tf32(v.z); v.w = to_tf32(v.w);                               \
        *(float4*)&sB[BUF][lr][lk4 * 4] = v;                                  \
    }

    const int nk = K / BK;
    DLOAD(0); DSTORE(0);
    __syncthreads();

    for (int it = 0; it < nk; it++) {
        const int buf = it & 1;
        if (it + 1 < nk) DLOAD((it + 1) * BK);

        unsigned af1[MT][4], af2[MT][4];
#pragma unroll
        for (int mt = 0; mt < MT; mt++) {
            int r = wm + mt * 16 + gid;
            af1[mt][0] = __float_as_uint(sA1[buf][r][tidg]);
            af1[mt][1] = __float_as_uint(sA1[buf][r + 8][tidg]);
            af1[mt][2] = __float_as_uint(sA1[buf][r][tidg + 4]);
            af1[mt][3] = __float_as_uint(sA1[buf][r + 8][tidg + 4]);
            af2[mt][0] = __float_as_uint(sA2[buf][r][tidg]);
            af2[mt][1] = __float_as_uint(sA2[buf][r + 8][tidg]);
            af2[mt][2] = __float_as_uint(sA2[buf][r][tidg + 4]);
            af2[mt][3] = __float_as_uint(sA2[buf][r + 8][tidg + 4]);
        }
        unsigned bf1[NT][2], bf2[NT][2];
#pragma unroll
        for (int nt = 0; nt < NT; nt++) {
            int n = wn + nt * 8 + gid;
            bf1[nt][0] = __float_as_uint(sB[buf][n][tidg]);
            bf1[nt][1] = __float_as_uint(sB[buf][n][tidg + 4]);
            bf2[nt][0] = __float_as_uint(sB[buf][n + BN][tidg]);
            bf2[nt][1] = __float_as_uint(sB[buf][n + BN][tidg + 4]);
        }
#pragma unroll
        for (int mt = 0; mt < MT; mt++)
#pragma unroll
            for (int nt = 0; nt < NT; nt++) {
                mma_tf32(acc1[mt][nt], af1[mt], bf1[nt]);
                mma_tf32(acc2[mt][nt], af2[mt], bf2[nt]);
            }

        if (it + 1 < nk) {
            DSTORE(buf ^ 1);
            __syncthreads();
        }
    }

#pragma unroll
    for (int mt = 0; mt < MT; mt++)
#pragma unroll
        for (int nt = 0; nt < NT; nt++) {
            int col = wn + nt * 8 + 2 * tidg;
#pragma unroll
            for (int half = 0; half < 2; half++) {
                int row = m0 + wm + mt * 16 + gid + half * 8;
                if (row >= M) continue;
                float xh0 = leaky_(acc1[mt][nt][half * 2 + 0] + b1[col])
                          + id_emb[(size_t)row * BN + col];
                float xh1 = leaky_(acc1[mt][nt][half * 2 + 1] + b1[col + 1])
                          + id_emb[(size_t)row * BN + col + 1];
                float v0 = leaky_(acc2[mt][nt][half * 2 + 0] + b2[col] + xh0);
                float v1 = leaky_(acc2[mt][nt][half * 2 + 1] + b2[col + 1] + xh1);
                *(float2*)&C[(size_t)row * BN + col] = make_float2(v0, v1);
            }
        }
#undef DLOAD
#undef DSTORE
}

// ---------------------------------------------------------------------------
// Fused copy + row-wise L2 normalize for preference rows (D=128, warp/row)
// ---------------------------------------------------------------------------
__global__ void pref_norm_kernel(const float* __restrict__ src,
                                 float* __restrict__ dst, int nrows)
{
    int warp = (blockIdx.x * blockDim.x + threadIdx.x) >> 5;
    int lane = threadIdx.x & 31;
    if (warp >= nrows) return;
    float4 v = *(const float4*)&src[(size_t)warp * 128 + lane * 4];
    float ss = v.x * v.x + v.y * v.y + v.z * v.z + v.w * v.w;
#pragma unroll
    for (int o = 16; o; o >>= 1) ss += __shfl_xor_sync(0xffffffffu, ss, o);
    float inv = 1.0f / fmaxf(sqrtf(ss), 1e-12f);
    v.x *= inv; v.y *= inv; v.z *= inv; v.w *= inv;
    *(float4*)&dst[(size_t)warp * 128 + lane * 4] = v;
}

// ---------------------------------------------------------------------------
// CSR build: histogram of dst, 3-phase exclusive scan, src reorder by dst
// ---------------------------------------------------------------------------
__global__ void hist_kernel(const int* __restrict__ ei, int* __restrict__ cnt)
{
    int e = blockIdx.x * blockDim.x + threadIdx.x;
    if (e < NE_) atomicAdd(&cnt[__ldg(&ei[NE_ + e])], 1);
}

__global__ void scan1_kernel(const int* __restrict__ in, int* __restrict__ out,
                             int* __restrict__ part, int n)
{
    __shared__ int s[1024];
    int i = blockIdx.x * 1024 + threadIdx.x;
    int v = (i < n) ? in[i] : 0;
    s[threadIdx.x] = v;
    __syncthreads();
#pragma unroll
    for (int o = 1; o < 1024; o <<= 1) {
        int y = (threadIdx.x >= o) ? s[threadIdx.x - o] : 0;
        __syncthreads();
        s[threadIdx.x] += y;
        __syncthreads();
    }
    if (i < n) out[i] = s[threadIdx.x] - v;     // exclusive
    if (threadIdx.x == 1023) part[blockIdx.x] = s[1023];
}

__global__ void scan2_kernel(int* __restrict__ part, int nb)
{
    if (threadIdx.x == 0 && blockIdx.x == 0) {
        int run = 0;
        for (int i = 0; i < nb; i++) { int v = part[i]; part[i] = run; run += v; }
    }
}

__global__ void scan3_kernel(int* __restrict__ out, const int* __restrict__ part, int n)
{
    int i = blockIdx.x * 1024 + threadIdx.x;
    if (i < n) out[i] += part[blockIdx.x];
}

__global__ void reorder_kernel(const int* __restrict__ ei, int* __restrict__ pos,
                               int* __restrict__ srcs)
{
    int e = blockIdx.x * blockDim.x + threadIdx.x;
    if (e >= NE_) return;
    int d = __ldg(&ei[NE_ + e]);
    int idx = atomicAdd(&pos[d], 1);
    srcs[idx] = __ldg(&ei[e]);
}

// ---------------------------------------------------------------------------
// Atomic-free segmented scatter over bf16 xw:
//   h[d] = sum_{e: dst=d} float(xw[srcs[e]])   (fp32 accumulate, fp32 out)
// Each lane handles a 4-element (8-byte) slice.
// ---------------------------------------------------------------------------
template <int D>
__global__ void seg_scatter(const __nv_bfloat16* __restrict__ xw,
                            const int* __restrict__ offs,
                            const int* __restrict__ srcs,
                            float* __restrict__ h)
{
    constexpr int G = D / 4;
    int gt   = blockIdx.x * blockDim.x + threadIdx.x;
    int node = gt / G;
    int q    = threadIdx.x % G;
    if (node >= NN_) return;

    int s   = __ldg(&offs[node]);
    int end = __ldg(&offs[node + 1]);

    float4 a0 = make_float4(0.f, 0.f, 0.f, 0.f);
    float4 a1 = make_float4(0.f, 0.f, 0.f, 0.f);

#define ACC(dstacc, u)                                                      \
    {                                                                       \
        float2 f0 = __bfloat1622float2(*(const __nv_bfloat162*)&(u).x);     \
        float2 f1 = __bfloat1622float2(*(const __nv_bfloat162*)&(u).y);     \
        dstacc.x += f0.x; dstacc.y += f0.y;                                 \
        dstacc.z += f1.x; dstacc.w += f1.y;                                 \
    }

    int i = s;
    for (; i + 3 < end; i += 4) {
        int s0 = __ldg(&srcs[i + 0]);
        int s1 = __ldg(&srcs[i + 1]);
        int s2 = __ldg(&srcs[i + 2]);
        int s3 = __ldg(&srcs[i + 3]);
        uint2 u0 = *(const uint2*)&xw[(size_t)s0 * D + q * 4];
        uint2 u1 = *(const uint2*)&xw[(size_t)s1 * D + q * 4];
        uint2 u2 = *(const uint2*)&xw[(size_t)s2 * D + q * 4];
        uint2 u3 = *(const uint2*)&xw[(size_t)s3 * D + q * 4];
        ACC(a0, u0); ACC(a1, u1); ACC(a0, u2); ACC(a1, u3);
    }
    for (; i < end; i++) {
        int s0 = __ldg(&srcs[i]);
        uint2 u0 = *(const uint2*)&xw[(size_t)s0 * D + q * 4];
        ACC(a0, u0);
    }
#undef ACC
    float4 r;
    r.x = a0.x + a1.x; r.y = a0.y + a1.y;
    r.z = a0.z + a1.z; r.w = a0.w + a1.w;
    *(float4*)&h[(size_t)node * D + q * 4] = r;
}

// ---------------------------------------------------------------------------
extern "C" void kernel_launch(void* const* d_in, const int* in_sizes, int n_in,
                              void* d_out, int out_size)
{
    const float* features = (const float*)d_in[0];
    const float* id_emb   = (const float*)d_in[1];
    const float* pref     = (const float*)d_in[2];
    const float* mlp_w    = (const float*)d_in[3];
    const float* mlp_b    = (const float*)d_in[4];
    const float* conv1_w  = (const float*)d_in[5];
    const float* lin1_w   = (const float*)d_in[6];
    const float* lin1_b   = (const float*)d_in[7];
    const float* g1_w     = (const float*)d_in[8];
    const float* g1_b     = (const float*)d_in[9];
    const float* conv2_w  = (const float*)d_in[10];
    const float* lin2_w   = (const float*)d_in[11];
    const float* lin2_b   = (const float*)d_in[12];
    const float* g2_w     = (const float*)d_in[13];
    const float* g2_b     = (const float*)d_in[14];
    const int*   ei       = (const int*)d_in[15];
    float* out = (float*)d_out;

    float *px, *ph, *px2;
    __nv_bfloat16* pxw;
    int *pcnt, *poffs, *ppart, *ppos, *psrcs;
    cudaGetSymbolAddress((void**)&px,    g_x);
    cudaGetSymbolAddress((void**)&pxw,   g_xw);
    cudaGetSymbolAddress((void**)&ph,    g_h);
    cudaGetSymbolAddress((void**)&px2,   g_x2);
    cudaGetSymbolAddress((void**)&pcnt,  g_cnt);
    cudaGetSymbolAddress((void**)&poffs, g_offs);
    cudaGetSymbolAddress((void**)&ppart, g_part);
    cudaGetSymbolAddress((void**)&ppos,  g_pos);
    cudaGetSymbolAddress((void**)&psrcs, g_srcs);

    const int GB_N  = (NN_ + 127) / 128;
    const int NSCAN = NN_ + 1;
    const int NBLK  = (NSCAN + 1023) / 1024;

    // Side stream for the CSR build (created once; fork/join via events is
    // the standard graph-capture pattern — kernels and event deps only).
    static cudaStream_t s_csr = nullptr;
    static cudaEvent_t ev_fork = nullptr, ev_join = nullptr;
    if (!s_csr) {
        cudaStreamCreateWithFlags(&s_csr, cudaStreamNonBlocking);
        cudaEventCreateWithFlags(&ev_fork, cudaEventDisableTiming);
        cudaEventCreateWithFlags(&ev_join, cudaEventDisableTiming);
    }

    // ---- fork: CSR build on side stream ----
    cudaEventRecord(ev_fork, 0);
    cudaStreamWaitEvent(s_csr, ev_fork, 0);
    cudaMemsetAsync(pcnt, 0, NSCAN * sizeof(int), s_csr);
    hist_kernel<<<(NE_ + 255) / 256, 256, 0, s_csr>>>(ei, pcnt);
    scan1_kernel<<<NBLK, 1024, 0, s_csr>>>(pcnt, poffs, ppart, NSCAN);
    scan2_kernel<<<1, 32, 0, s_csr>>>(ppart, NBLK);
    scan3_kernel<<<NBLK, 1024, 0, s_csr>>>(poffs, ppart, NSCAN);
    cudaMemcpyAsync(ppos, poffs, NN_ * sizeof(int), cudaMemcpyDeviceToDevice, s_csr);
    reorder_kernel<<<(NE_ + 255) / 256, 256, 0, s_csr>>>(ei, ppos, psrcs);
    cudaEventRecord(ev_join, s_csr);

    // ---- main stream: feature pipeline ----
    pref_norm_kernel<<<(NU_ * 32 + 255) / 256, 256>>>(pref, px, NU_);
    mma_gemm<128, true, true, false><<<(NI_ + 127) / 128, 256>>>(
        features, mlp_w, px + (size_t)NU_ * DL_, NI_, DF_, mlp_b);

    // ===== layer 1 =====
    mma_gemm<128, false, false, true><<<GB_N, 256>>>(
        px, conv1_w, pxw, NN_, DL_, nullptr);
    cudaStreamWaitEvent(0, ev_join, 0);   // join CSR before scatter
    seg_scatter<128><<<(NN_ * 32 + 255) / 256, 256>>>(pxw, poffs, psrcs, ph);
    dual_gemm<<<GB_N, 256>>>(px, ph, lin1_w, g1_w, lin1_b, g1_b, id_emb, px2, NN_, DL_);

    // ===== layer 2 =====
    mma_gemm<64, false, false, true><<<GB_N, 256>>>(
        px2, conv2_w, pxw, NN_, DI_, nullptr);
    seg_scatter<64><<<(NN_ * 16 + 255) / 256, 256>>>(pxw, poffs, psrcs, ph);
    dual_gemm<<<GB_N, 256>>>(px2, ph, lin2_w, g2_w, lin2_b, g2_b, id_emb, out, NN_, DI_);
}